// round 11
// baseline (speedup 1.0000x reference)
#include <cuda_runtime.h>
#include <cuda_bf16.h>
#include <cuda_fp16.h>
#include <math_constants.h>

#define N_SRC 50000
#define N_DST 50000
#define NEDGE 800000
#define D_IN  256
#define H     8
#define D     32
#define HD    256
#define NEG   0.2f
#define NCHUNK ((N_DST + 255) / 256)   // 196

// ---------------- scratch (device globals) ----------------------------------
__device__ __align__(16) __half g_fs[(size_t)N_SRC * HD];  // 25.6 MB fp16 fs
__device__ float g_esrc[N_SRC * H];
__device__ float g_edst[N_DST * H];
__device__ float g_wesrc[H * D_IN];              // folded [h][k]
__device__ float g_wedst[H * D_IN];
__device__ int   g_count[N_DST];
__device__ int   g_off[N_DST + 1];
__device__ int   g_cursor[N_DST];
__device__ int   g_srcs[NEDGE];                  // CSR: src id per slot
__device__ int   g_part[NCHUNK];
__device__ __align__(16) __nv_bfloat16 g_Bth[256 * 256];  // src_w^T hi [n][k]
__device__ __align__(16) __nv_bfloat16 g_Btl[256 * 256];  // src_w^T lo [n][k]

// ---------------- 1. fold rel weights + zero counts + split/transpose B --------
__global__ void prep_kernel(const float* __restrict__ rel_emb,
                            const float* __restrict__ rel_w,
                            const float* __restrict__ src_w,
                            const float* __restrict__ dst_w) {
    int gi = blockIdx.x * blockDim.x + threadIdx.x;
    for (int i = gi; i < N_DST; i += gridDim.x * blockDim.x) g_count[i] = 0;

    for (int idx = gi; idx < 256 * 256; idx += gridDim.x * blockDim.x) {
        int k = idx >> 8, n = idx & 255;
        float v = src_w[idx];
        __nv_bfloat16 hh = __float2bfloat16_rn(v);
        g_Bth[n * 256 + k] = hh;
        g_Btl[n * 256 + k] = __float2bfloat16_rn(v - __bfloat162float(hh));
    }

    if (blockIdx.x == 0) {
        __shared__ float s_rel[H * 2 * D];  // 512
        int tid = threadIdx.x;
        for (int t = tid; t < 512; t += 256) {
            float s = 0.f;
            for (int r = 0; r < 64; r++) s += rel_emb[r] * rel_w[r * 512 + t];
            s_rel[t] = s;
        }
        __syncthreads();
        for (int t = tid; t < H * D_IN; t += 256) {
            int h = t >> 8, k = t & 255;
            float s1 = 0.f, s2 = 0.f;
#pragma unroll
            for (int d = 0; d < D; d++) {
                s1 += src_w[(size_t)k * 256 + h * 32 + d] * s_rel[h * 64 + 32 + d];
                s2 += dst_w[(size_t)k * 256 + h * 32 + d] * s_rel[h * 64 + d];
            }
            g_wesrc[h * 256 + k] = s1;
            g_wedst[h * 256 + k] = s2;
        }
    }
}

// ---------------- 2. e_src / e_dst GEMV (fused, 8 cols each) ------------------
__global__ __launch_bounds__(256) void gemv8(const float* __restrict__ feat_src,
                                             const float* __restrict__ feat_dst) {
    __shared__ float sw[H * D_IN];
    int which = blockIdx.y;
    const float* feat = which ? feat_dst : feat_src;
    const float* w = which ? g_wedst : g_wesrc;
    float* out = which ? g_edst : g_esrc;
    for (int t = threadIdx.x; t < H * D_IN; t += 256) sw[t] = w[t];
    __syncthreads();
    int warp = threadIdx.x >> 5, lane = threadIdx.x & 31;
    int row = blockIdx.x * 8 + warp;
    if (row >= N_SRC) return;
    float acc[8] = {0, 0, 0, 0, 0, 0, 0, 0};
    const float* fr = feat + (size_t)row * 256;
    for (int k = lane; k < 256; k += 32) {
        float f = fr[k];
#pragma unroll
        for (int h = 0; h < 8; h++) acc[h] += f * sw[h * 256 + k];
    }
#pragma unroll
    for (int h = 0; h < 8; h++)
#pragma unroll
        for (int o = 16; o; o >>= 1) acc[h] += __shfl_xor_sync(~0u, acc[h], o);
    if (lane == 0) {
#pragma unroll
        for (int h = 0; h < 8; h++) out[row * 8 + h] = acc[h];
    }
}

// ---------------- 3. degree histogram -----------------------------------------
__global__ __launch_bounds__(256) void hist_kernel(const int* __restrict__ dst_idx) {
    int e = blockIdx.x * 256 + threadIdx.x;
    if (e < NEDGE) atomicAdd(&g_count[dst_idx[e]], 1);
}

// ---------------- 4. fs = feat_src @ src_w  (bf16 hi/lo, double-buffered) ------
__device__ __forceinline__ void mma16816(float* c, unsigned a0, unsigned a1,
                                         unsigned a2, unsigned a3,
                                         unsigned b0, unsigned b1) {
    asm("mma.sync.aligned.m16n8k16.row.col.f32.bf16.bf16.f32 "
        "{%0,%1,%2,%3},{%4,%5,%6,%7},{%8,%9},{%0,%1,%2,%3};"
        : "+f"(c[0]), "+f"(c[1]), "+f"(c[2]), "+f"(c[3])
        : "r"(a0), "r"(a1), "r"(a2), "r"(a3), "r"(b0), "r"(b1));
}
__device__ __forceinline__ void ldsm4(unsigned& r0, unsigned& r1, unsigned& r2,
                                      unsigned& r3, unsigned addr) {
    asm volatile("ldmatrix.sync.aligned.m8n8.x4.shared.b16 {%0,%1,%2,%3}, [%4];"
                 : "=r"(r0), "=r"(r1), "=r"(r2), "=r"(r3) : "r"(addr));
}

#define A_PLANE (128 * 40 * 2)   // 10240 B
#define B_PLANE (64 * 40 * 2)    // 5120 B

__global__ __launch_bounds__(256, 2) void gemm_bf16(const float* __restrict__ A) {
    // 128x64 block tile, K-step 32, DOUBLE-BUFFERED smem (one barrier per tile).
    __shared__ __align__(16) __nv_bfloat16 sAh[2][128][40], sAl[2][128][40];
    __shared__ __align__(16) __nv_bfloat16 sBh[2][64][40],  sBl[2][64][40];

    const int tid = threadIdx.x;
    const int bm = blockIdx.x * 128;
    const int bn = blockIdx.y * 64;
    const int wid = tid >> 5, lane = tid & 31;
    const int wm = wid & 3, wn = wid >> 2;

    float c[2][4][4];
#pragma unroll
    for (int i = 0; i < 2; i++)
#pragma unroll
        for (int j = 0; j < 4; j++)
#pragma unroll
            for (int k = 0; k < 4; k++) c[i][j][k] = 0.f;

    float4 pa[4];
    uint4 pbh, pbl;
#pragma unroll
    for (int i = 0; i < 4; i++) {
        int q = tid + 256 * i;
        int r = q >> 3, c4 = (q & 7) * 4;
        int row = bm + r;
        pa[i] = (row < N_SRC) ? *(const float4*)(A + (size_t)row * 256 + c4)
                              : make_float4(0.f, 0.f, 0.f, 0.f);
    }
    {
        int n = tid >> 2, kc = (tid & 3) * 8;
        pbh = *(const uint4*)(g_Bth + (size_t)(bn + n) * 256 + kc);
        pbl = *(const uint4*)(g_Btl + (size_t)(bn + n) * 256 + kc);
    }

    const unsigned sAh_b = (unsigned)__cvta_generic_to_shared(&sAh[0][0][0]);
    const unsigned sAl_b = (unsigned)__cvta_generic_to_shared(&sAl[0][0][0]);
    const unsigned sBh_b = (unsigned)__cvta_generic_to_shared(&sBh[0][0][0]);
    const unsigned sBl_b = (unsigned)__cvta_generic_to_shared(&sBl[0][0][0]);
    const int l = lane;
    const unsigned aoff =
        (((wm * 32 + (l & 7) + ((l >> 3) & 1) * 8) * 40) + ((l >> 4) & 1) * 8) * 2;
    const unsigned boff =
        (((wn * 32 + (l & 7) + ((l >> 4) & 1) * 8) * 40) + ((l >> 3) & 1) * 8) * 2;

    // stage tile 0 into buffer 0
#pragma unroll
    for (int i = 0; i < 4; i++) {
        int q = tid + 256 * i;
        int r = q >> 3, c4 = (q & 7) * 4;
        float4 v = pa[i];
        __nv_bfloat162 h01 = __floats2bfloat162_rn(v.x, v.y);
        __nv_bfloat162 h23 = __floats2bfloat162_rn(v.z, v.w);
        *(__nv_bfloat162*)&sAh[0][r][c4] = h01;
        *(__nv_bfloat162*)&sAh[0][r][c4 + 2] = h23;
        *(__nv_bfloat162*)&sAl[0][r][c4] = __floats2bfloat162_rn(
            v.x - __bfloat162float(h01.x), v.y - __bfloat162float(h01.y));
        *(__nv_bfloat162*)&sAl[0][r][c4 + 2] = __floats2bfloat162_rn(
            v.z - __bfloat162float(h23.x), v.w - __bfloat162float(h23.y));
    }
    {
        int n = tid >> 2, kc = (tid & 3) * 8;
        *(uint4*)&sBh[0][n][kc] = pbh;
        *(uint4*)&sBl[0][n][kc] = pbl;
    }
    __syncthreads();

    for (int kt = 0; kt < 8; kt++) {
        const int buf = kt & 1;
        const unsigned abase = buf * A_PLANE;
        const unsigned bbase = buf * B_PLANE;

        if (kt < 7) {
            // issue global loads for tile kt+1 (consumed after compute)
#pragma unroll
            for (int i = 0; i < 4; i++) {
                int q = tid + 256 * i;
                int r = q >> 3, c4 = (q & 7) * 4;
                int row = bm + r;
                pa[i] = (row < N_SRC)
                            ? *(const float4*)(A + (size_t)row * 256 + (kt + 1) * 32 + c4)
                            : make_float4(0.f, 0.f, 0.f, 0.f);
            }
            int n = tid >> 2, kc = (tid & 3) * 8;
            pbh = *(const uint4*)(g_Bth + (size_t)(bn + n) * 256 + (kt + 1) * 32 + kc);
            pbl = *(const uint4*)(g_Btl + (size_t)(bn + n) * 256 + (kt + 1) * 32 + kc);
        }

        // compute on buffer `buf`
#pragma unroll
        for (int s = 0; s < 2; s++) {
            unsigned ah[2][4], al[2][4], bh[4][2], bl[4][2];
#pragma unroll
            for (int ia = 0; ia < 2; ia++) {
                unsigned off = aoff + (ia * 640 + s * 16) * 2 + abase;
                ldsm4(ah[ia][0], ah[ia][1], ah[ia][2], ah[ia][3], sAh_b + off);
                ldsm4(al[ia][0], al[ia][1], al[ia][2], al[ia][3], sAl_b + off);
            }
#pragma unroll
            for (int p = 0; p < 2; p++) {
                unsigned off = boff + (p * 640 + s * 16) * 2 + bbase;
                ldsm4(bh[2 * p][0], bh[2 * p][1], bh[2 * p + 1][0], bh[2 * p + 1][1],
                      sBh_b + off);
                ldsm4(bl[2 * p][0], bl[2 * p][1], bl[2 * p + 1][0], bl[2 * p + 1][1],
                      sBl_b + off);
            }
#pragma unroll
            for (int ia = 0; ia < 2; ia++)
#pragma unroll
                for (int ja = 0; ja < 4; ja++) {
                    mma16816(c[ia][ja], ah[ia][0], ah[ia][1], ah[ia][2], ah[ia][3],
                             bh[ja][0], bh[ja][1]);
                    mma16816(c[ia][ja], ah[ia][0], ah[ia][1], ah[ia][2], ah[ia][3],
                             bl[ja][0], bl[ja][1]);
                    mma16816(c[ia][ja], al[ia][0], al[ia][1], al[ia][2], al[ia][3],
                             bh[ja][0], bh[ja][1]);
                }
        }

        if (kt < 7) {
            // stage tile kt+1 into the other buffer (freed by the last barrier)
            const int nb = (kt + 1) & 1;
#pragma unroll
            for (int i = 0; i < 4; i++) {
                int q = tid + 256 * i;
                int r = q >> 3, c4 = (q & 7) * 4;
                float4 v = pa[i];
                __nv_bfloat162 h01 = __floats2bfloat162_rn(v.x, v.y);
                __nv_bfloat162 h23 = __floats2bfloat162_rn(v.z, v.w);
                *(__nv_bfloat162*)&sAh[nb][r][c4] = h01;
                *(__nv_bfloat162*)&sAh[nb][r][c4 + 2] = h23;
                *(__nv_bfloat162*)&sAl[nb][r][c4] = __floats2bfloat162_rn(
                    v.x - __bfloat162float(h01.x), v.y - __bfloat162float(h01.y));
                *(__nv_bfloat162*)&sAl[nb][r][c4 + 2] = __floats2bfloat162_rn(
                    v.z - __bfloat162float(h23.x), v.w - __bfloat162float(h23.y));
            }
            int n = tid >> 2, kc = (tid & 3) * 8;
            *(uint4*)&sBh[nb][n][kc] = pbh;
            *(uint4*)&sBl[nb][n][kc] = pbl;
            __syncthreads();
        }
    }

    // epilogue: fp32 accumulators -> fp16 fs
    const int tq = lane >> 2, tr = lane & 3;
#pragma unroll
    for (int ia = 0; ia < 2; ia++) {
        int row0 = bm + wm * 32 + ia * 16 + tq;
#pragma unroll
        for (int ja = 0; ja < 4; ja++) {
            int col = bn + wn * 32 + ja * 8 + 2 * tr;
            if (row0 < N_SRC)
                *(__half2*)&g_fs[(size_t)row0 * 256 + col] =
                    __floats2half2_rn(c[ia][ja][0], c[ia][ja][1]);
            if (row0 + 8 < N_SRC)
                *(__half2*)&g_fs[(size_t)(row0 + 8) * 256 + col] =
                    __floats2half2_rn(c[ia][ja][2], c[ia][ja][3]);
        }
    }
}

// ---------------- 5. three-phase exclusive scan ---------------------------------
__global__ __launch_bounds__(256) void scanA_kernel() {
    __shared__ int sh[256];
    int t = threadIdx.x;
    int i = blockIdx.x * 256 + t;
    sh[t] = (i < N_DST) ? g_count[i] : 0;
    __syncthreads();
#pragma unroll
    for (int off = 128; off; off >>= 1) {
        if (t < off) sh[t] += sh[t + off];
        __syncthreads();
    }
    if (t == 0) g_part[blockIdx.x] = sh[0];
}

__global__ __launch_bounds__(256) void scanB_kernel() {
    __shared__ int sh[256];
    int t = threadIdx.x;
    int v = (t < NCHUNK) ? g_part[t] : 0;
    sh[t] = v;
    __syncthreads();
#pragma unroll
    for (int off = 1; off < 256; off <<= 1) {
        int x = (t >= off) ? sh[t - off] : 0;
        __syncthreads();
        sh[t] += x;
        __syncthreads();
    }
    if (t < NCHUNK) g_part[t] = sh[t] - v;
    if (t == 255) g_off[N_DST] = sh[255];
}

__global__ __launch_bounds__(256) void scanC_kernel() {
    __shared__ int sh[256];
    int t = threadIdx.x;
    int i = blockIdx.x * 256 + t;
    int v = (i < N_DST) ? g_count[i] : 0;
    sh[t] = v;
    __syncthreads();
#pragma unroll
    for (int off = 1; off < 256; off <<= 1) {
        int x = (t >= off) ? sh[t - off] : 0;
        __syncthreads();
        sh[t] += x;
        __syncthreads();
    }
    if (i < N_DST) {
        int excl = sh[t] - v + g_part[blockIdx.x];
        g_off[i] = excl;
        g_cursor[i] = excl;
    }
}

// ---------------- 6. scatter src ids into CSR slots ----------------------------
__global__ __launch_bounds__(256) void scatter_kernel(const int* __restrict__ src_idx,
                                                      const int* __restrict__ dst_idx) {
    int e = blockIdx.x * 256 + threadIdx.x;
    if (e >= NEDGE) return;
    int t = dst_idx[e];
    int p = atomicAdd(&g_cursor[t], 1);
    g_srcs[p] = src_idx[e];
}

// ---------------- 7. softmax + aggregation (fp16 fs, cross-iter pipeline) ------
__global__ __launch_bounds__(256) void edge_agg(float* __restrict__ out) {
    int warp = threadIdx.x >> 5, lane = threadIdx.x & 31;
    int dst = blockIdx.x * 8 + warp;
    if (dst >= N_DST) return;
    const int beg = g_off[dst], end = g_off[dst + 1];
    const int h = lane >> 2;
    const float ed = g_edst[dst * 8 + h];
    const int col = lane * 8;

    float dsum = 0.f;
    float acc0 = 0, acc1 = 0, acc2 = 0, acc3 = 0, acc4 = 0, acc5 = 0, acc6 = 0, acc7 = 0;

#define ACC_EDGE(u, a)                                                        \
        {                                                                     \
            float2 p0 = __half22float2(*(const __half2*)&(u).x);              \
            float2 p1 = __half22float2(*(const __half2*)&(u).y);              \
            float2 p2 = __half22float2(*(const __half2*)&(u).z);              \
            float2 p3 = __half22float2(*(const __half2*)&(u).w);              \
            acc0 += (a) * p0.x; acc1 += (a) * p0.y;                           \
            acc2 += (a) * p1.x; acc3 += (a) * p1.y;                           \
            acc4 += (a) * p2.x; acc5 += (a) * p2.y;                           \
            acc6 += (a) * p3.x; acc7 += (a) * p3.y;                           \
        }

    int i = beg;
    int s0 = 0, s1 = 0, s2 = 0, s3 = 0;
    float e0 = 0, e1 = 0, e2 = 0, e3 = 0;
    if (i + 4 <= end) {
        s0 = __ldg(&g_srcs[i]);     s1 = __ldg(&g_srcs[i + 1]);
        s2 = __ldg(&g_srcs[i + 2]); s3 = __ldg(&g_srcs[i + 3]);
        e0 = __ldg(&g_esrc[s0 * 8 + h]); e1 = __ldg(&g_esrc[s1 * 8 + h]);
        e2 = __ldg(&g_esrc[s2 * 8 + h]); e3 = __ldg(&g_esrc[s3 * 8 + h]);
    }
    while (i + 4 <= end) {
        // fs loads for the CURRENT group (srcs already in registers)
        uint4 u0 = *(const uint4*)(g_fs + (size_t)s0 * 256 + col);
        uint4 u1 = *(const uint4*)(g_fs + (size_t)s1 * 256 + col);
        uint4 u2 = *(const uint4*)(g_fs + (size_t)s2 * 256 + col);
        uint4 u3 = *(const uint4*)(g_fs + (size_t)s3 * 256 + col);
        // prefetch NEXT group's srcs + esrc (overlaps with math below)
        int ni = i + 4;
        int t0 = 0, t1 = 0, t2 = 0, t3 = 0;
        float f0 = 0, f1 = 0, f2 = 0, f3 = 0;
        if (ni + 4 <= end) {
            t0 = __ldg(&g_srcs[ni]);     t1 = __ldg(&g_srcs[ni + 1]);
            t2 = __ldg(&g_srcs[ni + 2]); t3 = __ldg(&g_srcs[ni + 3]);
            f0 = __ldg(&g_esrc[t0 * 8 + h]); f1 = __ldg(&g_esrc[t1 * 8 + h]);
            f2 = __ldg(&g_esrc[t2 * 8 + h]); f3 = __ldg(&g_esrc[t3 * 8 + h]);
        }
        float v0 = e0 + ed; v0 = v0 > 0.f ? v0 : NEG * v0;
        float v1 = e1 + ed; v1 = v1 > 0.f ? v1 : NEG * v1;
        float v2 = e2 + ed; v2 = v2 > 0.f ? v2 : NEG * v2;
        float v3 = e3 + ed; v3 = v3 > 0.f ? v3 : NEG * v3;
        float a0 = __expf(v0), a1 = __expf(v1), a2 = __expf(v2), a3 = __expf(v3);
        dsum += (a0 + a1) + (a2 + a3);
        ACC_EDGE(u0, a0)
        ACC_EDGE(u1, a1)
        ACC_EDGE(u2, a2)
        ACC_EDGE(u3, a3)
        i = ni;
        s0 = t0; s1 = t1; s2 = t2; s3 = t3;
        e0 = f0; e1 = f1; e2 = f2; e3 = f3;
    }
    for (; i < end; i++) {
        int s = __ldg(&g_srcs[i]);
        float es = __ldg(&g_esrc[s * 8 + h]);
        float v = es + ed;
        v = v > 0.f ? v : NEG * v;
        float a = __expf(v);
        dsum += a;
        uint4 u = *(const uint4*)(g_fs + (size_t)s * 256 + col);
        ACC_EDGE(u, a)
    }
#undef ACC_EDGE
    const float dinv = 1.0f / dsum;
    float4* o = (float4*)(out + (size_t)dst * 256 + col);
    // fmaxf(NaN, 0) == 0 handles the empty-segment (0 * inf) case
    o[0] = make_float4(fmaxf(acc0 * dinv, 0.f), fmaxf(acc1 * dinv, 0.f),
                       fmaxf(acc2 * dinv, 0.f), fmaxf(acc3 * dinv, 0.f));
    o[1] = make_float4(fmaxf(acc4 * dinv, 0.f), fmaxf(acc5 * dinv, 0.f),
                       fmaxf(acc6 * dinv, 0.f), fmaxf(acc7 * dinv, 0.f));
}

// ---------------- launch --------------------------------------------------------
extern "C" void kernel_launch(void* const* d_in, const int* in_sizes, int n_in,
                              void* d_out, int out_size) {
    const float* feat_src = (const float*)d_in[0];
    const float* feat_dst = (const float*)d_in[1];
    const float* src_w    = (const float*)d_in[2];
    const float* dst_w    = (const float*)d_in[3];
    const float* rel_emb  = (const float*)d_in[4];
    const float* rel_w    = (const float*)d_in[5];
    const int*   src_idx  = (const int*)d_in[6];
    const int*   dst_idx  = (const int*)d_in[7];
    float* out = (float*)d_out;

    prep_kernel<<<64, 256>>>(rel_emb, rel_w, src_w, dst_w);
    gemv8<<<dim3((N_SRC + 7) / 8, 2), 256>>>(feat_src, feat_dst);
    hist_kernel<<<(NEDGE + 255) / 256, 256>>>(dst_idx);
    gemm_bf16<<<dim3((N_SRC + 127) / 128, 4), 256>>>(feat_src);   // profiled slot
    scanA_kernel<<<NCHUNK, 256>>>();
    scanB_kernel<<<1, 256>>>();
    scanC_kernel<<<NCHUNK, 256>>>();
    scatter_kernel<<<(NEDGE + 255) / 256, 256>>>(src_idx, dst_idx);
    edge_agg<<<(N_DST + 7) / 8, 256>>>(out);
}

// round 12
// speedup vs baseline: 1.2704x; 1.2704x over previous
#include <cuda_runtime.h>
#include <cuda_bf16.h>
#include <cuda_fp16.h>
#include <math_constants.h>

#define N_SRC 50000
#define N_DST 50000
#define NEDGE 800000
#define D_IN  256
#define H     8
#define D     32
#define HD    256
#define NEG   0.2f
#define NCHUNK ((N_DST + 255) / 256)   // 196

// ---------------- scratch (device globals) ----------------------------------
__device__ __align__(16) __half g_fs[(size_t)N_SRC * HD];  // 25.6 MB fp16 fs
__device__ float g_esrc[N_SRC * H];
__device__ float g_edst[N_DST * H];
__device__ float g_wedst[H * D_IN];              // folded [h][k]
__device__ float g_relE[256];                    // relE[col] = rel[col/32][D+col%32]
__device__ int   g_count[N_DST];
__device__ int   g_off[N_DST + 1];
__device__ int   g_cursor[N_DST];
__device__ int   g_srcs[NEDGE];                  // CSR: src id per slot
__device__ int   g_part[NCHUNK];
__device__ __align__(16) __nv_bfloat16 g_Bth[256 * 256];  // src_w^T hi [n][k]
__device__ __align__(16) __nv_bfloat16 g_Btl[256 * 256];  // src_w^T lo [n][k]

// ---------------- 1. prep: fold rel, zero counts, split/transpose B, relE ------
__global__ void prep_kernel(const float* __restrict__ rel_emb,
                            const float* __restrict__ rel_w,
                            const float* __restrict__ src_w,
                            const float* __restrict__ dst_w) {
    int gi = blockIdx.x * blockDim.x + threadIdx.x;
    for (int i = gi; i < N_DST; i += gridDim.x * blockDim.x) g_count[i] = 0;

    for (int idx = gi; idx < 256 * 256; idx += gridDim.x * blockDim.x) {
        int k = idx >> 8, n = idx & 255;
        float v = src_w[idx];
        __nv_bfloat16 hh = __float2bfloat16_rn(v);
        g_Bth[n * 256 + k] = hh;
        g_Btl[n * 256 + k] = __float2bfloat16_rn(v - __bfloat162float(hh));
    }

    if (blockIdx.x == 0) {
        __shared__ float s_rel[H * 2 * D];  // 512
        int tid = threadIdx.x;
        for (int t = tid; t < 512; t += 256) {
            float s = 0.f;
            for (int r = 0; r < 64; r++) s += rel_emb[r] * rel_w[r * 512 + t];
            s_rel[t] = s;
        }
        __syncthreads();
        // relE for the gemm e_src epilogue
        if (tid < 256) g_relE[tid] = s_rel[(tid >> 5) * 64 + 32 + (tid & 31)];
        // folded dst weights for the gemv
        for (int t = tid; t < H * D_IN; t += 256) {
            int h = t >> 8, k = t & 255;
            float s2 = 0.f;
#pragma unroll
            for (int d = 0; d < D; d++)
                s2 += dst_w[(size_t)k * 256 + h * 32 + d] * s_rel[h * 64 + d];
            g_wedst[h * 256 + k] = s2;
        }
    }
}

// ---------------- 2. e_dst GEMV (8 cols) ----------------------------------------
__global__ __launch_bounds__(256) void gemv_dst(const float* __restrict__ feat_dst) {
    __shared__ float sw[H * D_IN];
    for (int t = threadIdx.x; t < H * D_IN; t += 256) sw[t] = g_wedst[t];
    __syncthreads();
    int warp = threadIdx.x >> 5, lane = threadIdx.x & 31;
    int row = blockIdx.x * 8 + warp;
    if (row >= N_DST) return;
    float acc[8] = {0, 0, 0, 0, 0, 0, 0, 0};
    const float* fr = feat_dst + (size_t)row * 256;
    for (int k = lane; k < 256; k += 32) {
        float f = fr[k];
#pragma unroll
        for (int h = 0; h < 8; h++) acc[h] += f * sw[h * 256 + k];
    }
#pragma unroll
    for (int h = 0; h < 8; h++)
#pragma unroll
        for (int o = 16; o; o >>= 1) acc[h] += __shfl_xor_sync(~0u, acc[h], o);
    if (lane == 0) {
#pragma unroll
        for (int h = 0; h < 8; h++) g_edst[row * 8 + h] = acc[h];
    }
}

// ---------------- 3. degree histogram -----------------------------------------
__global__ __launch_bounds__(256) void hist_kernel(const int* __restrict__ dst_idx) {
    int e = blockIdx.x * 256 + threadIdx.x;
    if (e < NEDGE) atomicAdd(&g_count[dst_idx[e]], 1);
}

// ---------------- 4. fs = feat_src @ src_w + fused e_src epilogue --------------
__device__ __forceinline__ void mma16816(float* c, unsigned a0, unsigned a1,
                                         unsigned a2, unsigned a3,
                                         unsigned b0, unsigned b1) {
    asm("mma.sync.aligned.m16n8k16.row.col.f32.bf16.bf16.f32 "
        "{%0,%1,%2,%3},{%4,%5,%6,%7},{%8,%9},{%0,%1,%2,%3};"
        : "+f"(c[0]), "+f"(c[1]), "+f"(c[2]), "+f"(c[3])
        : "r"(a0), "r"(a1), "r"(a2), "r"(a3), "r"(b0), "r"(b1));
}
__device__ __forceinline__ void ldsm4(unsigned& r0, unsigned& r1, unsigned& r2,
                                      unsigned& r3, unsigned addr) {
    asm volatile("ldmatrix.sync.aligned.m8n8.x4.shared.b16 {%0,%1,%2,%3}, [%4];"
                 : "=r"(r0), "=r"(r1), "=r"(r2), "=r"(r3) : "r"(addr));
}

__global__ __launch_bounds__(256, 2) void gemm_bf16(const float* __restrict__ A) {
    __shared__ __align__(16) __nv_bfloat16 sAh[128][40], sAl[128][40];  // [m][k]
    __shared__ __align__(16) __nv_bfloat16 sBh[64][40], sBl[64][40];    // [n][k]

    const int tid = threadIdx.x;
    const int bm = blockIdx.x * 128;
    const int bn = blockIdx.y * 64;
    const int wid = tid >> 5, lane = tid & 31;
    const int wm = wid & 3, wn = wid >> 2;

    float c[2][4][4];
#pragma unroll
    for (int i = 0; i < 2; i++)
#pragma unroll
        for (int j = 0; j < 4; j++)
#pragma unroll
            for (int k = 0; k < 4; k++) c[i][j][k] = 0.f;

    float4 pa[4];
    uint4 pbh, pbl;
#pragma unroll
    for (int i = 0; i < 4; i++) {
        int q = tid + 256 * i;
        int r = q >> 3, c4 = (q & 7) * 4;
        int row = bm + r;
        pa[i] = (row < N_SRC) ? *(const float4*)(A + (size_t)row * 256 + c4)
                              : make_float4(0.f, 0.f, 0.f, 0.f);
    }
    {
        int n = tid >> 2, kc = (tid & 3) * 8;
        pbh = *(const uint4*)(g_Bth + (size_t)(bn + n) * 256 + kc);
        pbl = *(const uint4*)(g_Btl + (size_t)(bn + n) * 256 + kc);
    }

    const unsigned sAh_b = (unsigned)__cvta_generic_to_shared(&sAh[0][0]);
    const unsigned sAl_b = (unsigned)__cvta_generic_to_shared(&sAl[0][0]);
    const unsigned sBh_b = (unsigned)__cvta_generic_to_shared(&sBh[0][0]);
    const unsigned sBl_b = (unsigned)__cvta_generic_to_shared(&sBl[0][0]);
    const int l = lane;
    const unsigned aoff =
        (((wm * 32 + (l & 7) + ((l >> 3) & 1) * 8) * 40) + ((l >> 4) & 1) * 8) * 2;
    const unsigned boff =
        (((wn * 32 + (l & 7) + ((l >> 4) & 1) * 8) * 40) + ((l >> 3) & 1) * 8) * 2;

    for (int kt = 0; kt < 8; kt++) {
#pragma unroll
        for (int i = 0; i < 4; i++) {
            int q = tid + 256 * i;
            int r = q >> 3, c4 = (q & 7) * 4;
            float4 v = pa[i];
            __nv_bfloat162 h01 = __floats2bfloat162_rn(v.x, v.y);
            __nv_bfloat162 h23 = __floats2bfloat162_rn(v.z, v.w);
            *(__nv_bfloat162*)&sAh[r][c4] = h01;
            *(__nv_bfloat162*)&sAh[r][c4 + 2] = h23;
            *(__nv_bfloat162*)&sAl[r][c4] = __floats2bfloat162_rn(
                v.x - __bfloat162float(h01.x), v.y - __bfloat162float(h01.y));
            *(__nv_bfloat162*)&sAl[r][c4 + 2] = __floats2bfloat162_rn(
                v.z - __bfloat162float(h23.x), v.w - __bfloat162float(h23.y));
        }
        {
            int n = tid >> 2, kc = (tid & 3) * 8;
            *(uint4*)&sBh[n][kc] = pbh;
            *(uint4*)&sBl[n][kc] = pbl;
        }
        __syncthreads();

        if (kt < 7) {
#pragma unroll
            for (int i = 0; i < 4; i++) {
                int q = tid + 256 * i;
                int r = q >> 3, c4 = (q & 7) * 4;
                int row = bm + r;
                pa[i] = (row < N_SRC)
                            ? *(const float4*)(A + (size_t)row * 256 + (kt + 1) * 32 + c4)
                            : make_float4(0.f, 0.f, 0.f, 0.f);
            }
            int n = tid >> 2, kc = (tid & 3) * 8;
            pbh = *(const uint4*)(g_Bth + (size_t)(bn + n) * 256 + (kt + 1) * 32 + kc);
            pbl = *(const uint4*)(g_Btl + (size_t)(bn + n) * 256 + (kt + 1) * 32 + kc);
        }

#pragma unroll
        for (int s = 0; s < 2; s++) {
            unsigned ah[2][4], al[2][4], bh[4][2], bl[4][2];
#pragma unroll
            for (int ia = 0; ia < 2; ia++) {
                unsigned off = aoff + (ia * 640 + s * 16) * 2;
                ldsm4(ah[ia][0], ah[ia][1], ah[ia][2], ah[ia][3], sAh_b + off);
                ldsm4(al[ia][0], al[ia][1], al[ia][2], al[ia][3], sAl_b + off);
            }
#pragma unroll
            for (int p = 0; p < 2; p++) {
                unsigned off = boff + (p * 640 + s * 16) * 2;
                ldsm4(bh[2 * p][0], bh[2 * p][1], bh[2 * p + 1][0], bh[2 * p + 1][1],
                      sBh_b + off);
                ldsm4(bl[2 * p][0], bl[2 * p][1], bl[2 * p + 1][0], bl[2 * p + 1][1],
                      sBl_b + off);
            }
#pragma unroll
            for (int ia = 0; ia < 2; ia++)
#pragma unroll
                for (int ja = 0; ja < 4; ja++) {
                    mma16816(c[ia][ja], ah[ia][0], ah[ia][1], ah[ia][2], ah[ia][3],
                             bh[ja][0], bh[ja][1]);
                    mma16816(c[ia][ja], ah[ia][0], ah[ia][1], ah[ia][2], ah[ia][3],
                             bl[ja][0], bl[ja][1]);
                    mma16816(c[ia][ja], al[ia][0], al[ia][1], al[ia][2], al[ia][3],
                             bh[ja][0], bh[ja][1]);
                }
        }
        if (kt < 7) __syncthreads();
    }

    // epilogue 1: fp32 accumulators -> fp16 fs
    const int tq = lane >> 2, tr = lane & 3;
#pragma unroll
    for (int ia = 0; ia < 2; ia++) {
        int row0 = bm + wm * 32 + ia * 16 + tq;
#pragma unroll
        for (int ja = 0; ja < 4; ja++) {
            int col = bn + wn * 32 + ja * 8 + 2 * tr;
            if (row0 < N_SRC)
                *(__half2*)&g_fs[(size_t)row0 * 256 + col] =
                    __floats2half2_rn(c[ia][ja][0], c[ia][ja][1]);
            if (row0 + 8 < N_SRC)
                *(__half2*)&g_fs[(size_t)(row0 + 8) * 256 + col] =
                    __floats2half2_rn(c[ia][ja][2], c[ia][ja][3]);
        }
    }

    // epilogue 2: fused e_src — this warp's 32 cols = exactly one head
    {
        const int hd = (bn + wn * 32) >> 5;
        float rE[8];
#pragma unroll
        for (int ja = 0; ja < 4; ja++) {
            int col = bn + wn * 32 + ja * 8 + 2 * tr;
            rE[ja * 2]     = g_relE[col];
            rE[ja * 2 + 1] = g_relE[col + 1];
        }
#pragma unroll
        for (int ia = 0; ia < 2; ia++) {
            float p0 = 0.f, p8 = 0.f;
#pragma unroll
            for (int ja = 0; ja < 4; ja++) {
                p0 += c[ia][ja][0] * rE[ja * 2] + c[ia][ja][1] * rE[ja * 2 + 1];
                p8 += c[ia][ja][2] * rE[ja * 2] + c[ia][ja][3] * rE[ja * 2 + 1];
            }
            p0 += __shfl_xor_sync(~0u, p0, 1);
            p0 += __shfl_xor_sync(~0u, p0, 2);
            p8 += __shfl_xor_sync(~0u, p8, 1);
            p8 += __shfl_xor_sync(~0u, p8, 2);
            int row0 = bm + wm * 32 + ia * 16 + tq;
            if (tr == 0) {
                if (row0 < N_SRC) g_esrc[row0 * 8 + hd] = p0;
                if (row0 + 8 < N_SRC) g_esrc[(row0 + 8) * 8 + hd] = p8;
            }
        }
    }
}

// ---------------- 5. three-phase exclusive scan ---------------------------------
__global__ __launch_bounds__(256) void scanA_kernel() {
    __shared__ int sh[256];
    int t = threadIdx.x;
    int i = blockIdx.x * 256 + t;
    sh[t] = (i < N_DST) ? g_count[i] : 0;
    __syncthreads();
#pragma unroll
    for (int off = 128; off; off >>= 1) {
        if (t < off) sh[t] += sh[t + off];
        __syncthreads();
    }
    if (t == 0) g_part[blockIdx.x] = sh[0];
}

__global__ __launch_bounds__(256) void scanB_kernel() {
    __shared__ int sh[256];
    int t = threadIdx.x;
    int v = (t < NCHUNK) ? g_part[t] : 0;
    sh[t] = v;
    __syncthreads();
#pragma unroll
    for (int off = 1; off < 256; off <<= 1) {
        int x = (t >= off) ? sh[t - off] : 0;
        __syncthreads();
        sh[t] += x;
        __syncthreads();
    }
    if (t < NCHUNK) g_part[t] = sh[t] - v;
    if (t == 255) g_off[N_DST] = sh[255];
}

__global__ __launch_bounds__(256) void scanC_kernel() {
    __shared__ int sh[256];
    int t = threadIdx.x;
    int i = blockIdx.x * 256 + t;
    int v = (i < N_DST) ? g_count[i] : 0;
    sh[t] = v;
    __syncthreads();
#pragma unroll
    for (int off = 1; off < 256; off <<= 1) {
        int x = (t >= off) ? sh[t - off] : 0;
        __syncthreads();
        sh[t] += x;
        __syncthreads();
    }
    if (i < N_DST) {
        int excl = sh[t] - v + g_part[blockIdx.x];
        g_off[i] = excl;
        g_cursor[i] = excl;
    }
}

// ---------------- 6. scatter src ids into CSR slots ----------------------------
__global__ __launch_bounds__(256) void scatter_kernel(const int* __restrict__ src_idx,
                                                      const int* __restrict__ dst_idx) {
    int e = blockIdx.x * 256 + threadIdx.x;
    if (e >= NEDGE) return;
    int t = dst_idx[e];
    int p = atomicAdd(&g_cursor[t], 1);
    g_srcs[p] = src_idx[e];
}

// ---------------- 7. fused softmax + aggregation (R10 structure, fp16 fs) ------
__global__ __launch_bounds__(256) void edge_agg(float* __restrict__ out) {
    int warp = threadIdx.x >> 5, lane = threadIdx.x & 31;
    int dst = blockIdx.x * 8 + warp;
    if (dst >= N_DST) return;
    const int beg = g_off[dst], end = g_off[dst + 1];
    const int h = lane >> 2;
    const float ed = g_edst[dst * 8 + h];
    const int col = lane * 8;

    float dsum = 0.f;
    float acc0 = 0, acc1 = 0, acc2 = 0, acc3 = 0, acc4 = 0, acc5 = 0, acc6 = 0, acc7 = 0;

    int i = beg;
    for (; i + 4 <= end; i += 4) {
        int s0 = __ldg(&g_srcs[i]);
        int s1 = __ldg(&g_srcs[i + 1]);
        int s2 = __ldg(&g_srcs[i + 2]);
        int s3 = __ldg(&g_srcs[i + 3]);
        float e0 = __ldg(&g_esrc[s0 * 8 + h]);
        float e1 = __ldg(&g_esrc[s1 * 8 + h]);
        float e2 = __ldg(&g_esrc[s2 * 8 + h]);
        float e3 = __ldg(&g_esrc[s3 * 8 + h]);
        uint4 u0 = *(const uint4*)(g_fs + (size_t)s0 * 256 + col);
        uint4 u1 = *(const uint4*)(g_fs + (size_t)s1 * 256 + col);
        uint4 u2 = *(const uint4*)(g_fs + (size_t)s2 * 256 + col);
        uint4 u3 = *(const uint4*)(g_fs + (size_t)s3 * 256 + col);
        float v0 = e0 + ed; v0 = v0 > 0.f ? v0 : NEG * v0;
        float v1 = e1 + ed; v1 = v1 > 0.f ? v1 : NEG * v1;
        float v2 = e2 + ed; v2 = v2 > 0.f ? v2 : NEG * v2;
        float v3 = e3 + ed; v3 = v3 > 0.f ? v3 : NEG * v3;
        float a0 = __expf(v0), a1 = __expf(v1), a2 = __expf(v2), a3 = __expf(v3);
        dsum += (a0 + a1) + (a2 + a3);
#define ACC_EDGE(u, a)                                                        \
        {                                                                     \
            float2 p0 = __half22float2(*(const __half2*)&(u).x);              \
            float2 p1 = __half22float2(*(const __half2*)&(u).y);              \
            float2 p2 = __half22float2(*(const __half2*)&(u).z);              \
            float2 p3 = __half22float2(*(const __half2*)&(u).w);              \
            acc0 += (a) * p0.x; acc1 += (a) * p0.y;                           \
            acc2 += (a) * p1.x; acc3 += (a) * p1.y;                           \
            acc4 += (a) * p2.x; acc5 += (a) * p2.y;                           \
            acc6 += (a) * p3.x; acc7 += (a) * p3.y;                           \
        }
        ACC_EDGE(u0, a0)
        ACC_EDGE(u1, a1)
        ACC_EDGE(u2, a2)
        ACC_EDGE(u3, a3)
    }
    for (; i < end; i++) {
        int s = __ldg(&g_srcs[i]);
        float es = __ldg(&g_esrc[s * 8 + h]);
        float v = es + ed;
        v = v > 0.f ? v : NEG * v;
        float a = __expf(v);
        dsum += a;
        uint4 u = *(const uint4*)(g_fs + (size_t)s * 256 + col);
        ACC_EDGE(u, a)
    }
#undef ACC_EDGE
    const float dinv = 1.0f / dsum;
    float4* o = (float4*)(out + (size_t)dst * 256 + col);
    // fmaxf(NaN, 0) == 0 handles the empty-segment (0 * inf) case
    o[0] = make_float4(fmaxf(acc0 * dinv, 0.f), fmaxf(acc1 * dinv, 0.f),
                       fmaxf(acc2 * dinv, 0.f), fmaxf(acc3 * dinv, 0.f));
    o[1] = make_float4(fmaxf(acc4 * dinv, 0.f), fmaxf(acc5 * dinv, 0.f),
                       fmaxf(acc6 * dinv, 0.f), fmaxf(acc7 * dinv, 0.f));
}

// ---------------- launch --------------------------------------------------------
extern "C" void kernel_launch(void* const* d_in, const int* in_sizes, int n_in,
                              void* d_out, int out_size) {
    const float* feat_src = (const float*)d_in[0];
    const float* feat_dst = (const float*)d_in[1];
    const float* src_w    = (const float*)d_in[2];
    const float* dst_w    = (const float*)d_in[3];
    const float* rel_emb  = (const float*)d_in[4];
    const float* rel_w    = (const float*)d_in[5];
    const int*   src_idx  = (const int*)d_in[6];
    const int*   dst_idx  = (const int*)d_in[7];
    float* out = (float*)d_out;

    prep_kernel<<<64, 256>>>(rel_emb, rel_w, src_w, dst_w);
    gemv_dst<<<(N_DST + 7) / 8, 256>>>(feat_dst);
    hist_kernel<<<(NEDGE + 255) / 256, 256>>>(dst_idx);
    gemm_bf16<<<dim3((N_SRC + 127) / 128, 4), 256>>>(feat_src);   // profiled slot
    scanA_kernel<<<NCHUNK, 256>>>();
    scanB_kernel<<<1, 256>>>();
    scanC_kernel<<<NCHUNK, 256>>>();
    scatter_kernel<<<(NEDGE + 255) / 256, 256>>>(src_idx, dst_idx);
    edge_agg<<<(N_DST + 7) / 8, 256>>>(out);
}

// round 14
// speedup vs baseline: 1.3429x; 1.0570x over previous
#include <cuda_runtime.h>
#include <cuda_fp16.h>
#include <math_constants.h>
#include <cstdint>

#define N_SRC 50000
#define N_DST 50000
#define NEDGE 800000
#define D_IN  256
#define H     8
#define D     32
#define HD    256
#define NEG   0.2f
#define NCHUNK ((N_DST + 255) / 256)   // 196

// ---------------- scratch (device globals) ----------------------------------
__device__ __align__(16) __half g_fs[(size_t)N_SRC * HD];  // 25.6 MB fp16 fs
__device__ float g_esrc[N_SRC * H];
__device__ float g_edst[N_DST * H];
__device__ float g_wedst[H * D_IN];              // folded [h][k]
__device__ float g_relE[256];                    // relE[col] = rel[col/32][D+col%32]
__device__ int   g_count[N_DST];
__device__ int   g_off[N_DST + 1];
__device__ int   g_cursor[N_DST];
__device__ int   g_srcs[NEDGE];                  // CSR: src id per slot
__device__ int   g_part[NCHUNK];
__device__ __align__(16) __half g_Bt[256 * 256]; // src_w^T fp16 [n][k]

// ---------------- 1. prep: fold rel, zero counts, transpose B fp16, relE -------
__global__ void prep_kernel(const float* __restrict__ rel_emb,
                            const float* __restrict__ rel_w,
                            const float* __restrict__ src_w,
                            const float* __restrict__ dst_w) {
    int gi = blockIdx.x * blockDim.x + threadIdx.x;
    for (int i = gi; i < N_DST; i += gridDim.x * blockDim.x) g_count[i] = 0;

    for (int idx = gi; idx < 256 * 256; idx += gridDim.x * blockDim.x) {
        int k = idx >> 8, n = idx & 255;
        g_Bt[n * 256 + k] = __float2half_rn(src_w[idx]);
    }

    if (blockIdx.x == 0) {
        __shared__ float s_rel[H * 2 * D];  // 512
        int tid = threadIdx.x;
        for (int t = tid; t < 512; t += 256) {
            float s = 0.f;
            for (int r = 0; r < 64; r++) s += rel_emb[r] * rel_w[r * 512 + t];
            s_rel[t] = s;
        }
        __syncthreads();
        if (tid < 256) g_relE[tid] = s_rel[(tid >> 5) * 64 + 32 + (tid & 31)];
        for (int t = tid; t < H * D_IN; t += 256) {
            int h = t >> 8, k = t & 255;
            float s2 = 0.f;
#pragma unroll
            for (int d = 0; d < D; d++)
                s2 += dst_w[(size_t)k * 256 + h * 32 + d] * s_rel[h * 64 + d];
            g_wedst[h * 256 + k] = s2;
        }
    }
}

// ---------------- 2. e_dst GEMV (8 cols) ----------------------------------------
__global__ __launch_bounds__(256) void gemv_dst(const float* __restrict__ feat_dst) {
    __shared__ float sw[H * D_IN];
    for (int t = threadIdx.x; t < H * D_IN; t += 256) sw[t] = g_wedst[t];
    __syncthreads();
    int warp = threadIdx.x >> 5, lane = threadIdx.x & 31;
    int row = blockIdx.x * 8 + warp;
    if (row >= N_DST) return;
    float acc[8] = {0, 0, 0, 0, 0, 0, 0, 0};
    const float* fr = feat_dst + (size_t)row * 256;
    for (int k = lane; k < 256; k += 32) {
        float f = fr[k];
#pragma unroll
        for (int h = 0; h < 8; h++) acc[h] += f * sw[h * 256 + k];
    }
#pragma unroll
    for (int h = 0; h < 8; h++)
#pragma unroll
        for (int o = 16; o; o >>= 1) acc[h] += __shfl_xor_sync(~0u, acc[h], o);
    if (lane == 0) {
#pragma unroll
        for (int h = 0; h < 8; h++) g_edst[row * 8 + h] = acc[h];
    }
}

// ---------------- 3. degree histogram -----------------------------------------
__global__ __launch_bounds__(256) void hist_kernel(const int* __restrict__ dst_idx) {
    int e = blockIdx.x * 256 + threadIdx.x;
    if (e < NEDGE) atomicAdd(&g_count[dst_idx[e]], 1);
}

// ---------------- 4. fs = feat_src @ src_w  (fp16: A=hi+lo exact, B fp16) ------
// D = (Ah+Al)·B : A error ~2^-22 (negligible), B error ~2e-4 RMS. 2 MMAs/k16.
__device__ __forceinline__ void mma16816h(float* c, unsigned a0, unsigned a1,
                                          unsigned a2, unsigned a3,
                                          unsigned b0, unsigned b1) {
    asm("mma.sync.aligned.m16n8k16.row.col.f32.f16.f16.f32 "
        "{%0,%1,%2,%3},{%4,%5,%6,%7},{%8,%9},{%0,%1,%2,%3};"
        : "+f"(c[0]), "+f"(c[1]), "+f"(c[2]), "+f"(c[3])
        : "r"(a0), "r"(a1), "r"(a2), "r"(a3), "r"(b0), "r"(b1));
}
__device__ __forceinline__ void ldsm4(unsigned& r0, unsigned& r1, unsigned& r2,
                                      unsigned& r3, unsigned addr) {
    asm volatile("ldmatrix.sync.aligned.m8n8.x4.shared.b16 {%0,%1,%2,%3}, [%4];"
                 : "=r"(r0), "=r"(r1), "=r"(r2), "=r"(r3) : "r"(addr));
}

__global__ __launch_bounds__(256, 2) void gemm_fp16(const float* __restrict__ A) {
    __shared__ __align__(16) __half sAh[128][40], sAl[128][40];  // [m][k]
    __shared__ __align__(16) __half sB[64][40];                  // [n][k]

    const int tid = threadIdx.x;
    const int bm = blockIdx.y * 128;
    const int bn = blockIdx.x * 64;
    const int wid = tid >> 5, lane = tid & 31;
    const int wm = wid & 3, wn = wid >> 2;   // 4x2 warp grid, warp tile 32x32

    float c[2][4][4];
#pragma unroll
    for (int i = 0; i < 2; i++)
#pragma unroll
        for (int j = 0; j < 4; j++)
#pragma unroll
            for (int k = 0; k < 4; k++) c[i][j][k] = 0.f;

    float4 pa[4];
    uint4 pb;
#pragma unroll
    for (int i = 0; i < 4; i++) {
        int q = tid + 256 * i;
        int r = q >> 3, c4 = (q & 7) * 4;
        int row = bm + r;
        pa[i] = (row < N_SRC) ? *(const float4*)(A + (size_t)row * 256 + c4)
                              : make_float4(0.f, 0.f, 0.f, 0.f);
    }
    {
        int n = tid >> 2, kc = (tid & 3) * 8;
        pb = *(const uint4*)(g_Bt + (size_t)(bn + n) * 256 + kc);
    }

    const unsigned sAh_b = (unsigned)__cvta_generic_to_shared(&sAh[0][0]);
    const unsigned sAl_b = (unsigned)__cvta_generic_to_shared(&sAl[0][0]);
    const unsigned sB_b = (unsigned)__cvta_generic_to_shared(&sB[0][0]);
    const int l = lane;
    const unsigned aoff =
        (((wm * 32 + (l & 7) + ((l >> 3) & 1) * 8) * 40) + ((l >> 4) & 1) * 8) * 2;
    const unsigned boff =
        (((wn * 32 + (l & 7) + ((l >> 4) & 1) * 8) * 40) + ((l >> 3) & 1) * 8) * 2;

    for (int kt = 0; kt < 8; kt++) {
        // A: convert fp32 -> fp16 hi/lo; B: plain 16B copy
#pragma unroll
        for (int i = 0; i < 4; i++) {
            int q = tid + 256 * i;
            int r = q >> 3, c4 = (q & 7) * 4;
            float4 v = pa[i];
            __half2 h01 = __floats2half2_rn(v.x, v.y);
            __half2 h23 = __floats2half2_rn(v.z, v.w);
            float lx = v.x - __low2float(h01);
            float ly = v.y - __high2float(h01);
            float lz = v.z - __low2float(h23);
            float lw = v.w - __high2float(h23);
            *(__half2*)&sAh[r][c4] = h01;
            *(__half2*)&sAh[r][c4 + 2] = h23;
            *(__half2*)&sAl[r][c4] = __floats2half2_rn(lx, ly);
            *(__half2*)&sAl[r][c4 + 2] = __floats2half2_rn(lz, lw);
        }
        {
            int n = tid >> 2, kc = (tid & 3) * 8;
            *(uint4*)&sB[n][kc] = pb;
        }
        __syncthreads();

        if (kt < 7) {
#pragma unroll
            for (int i = 0; i < 4; i++) {
                int q = tid + 256 * i;
                int r = q >> 3, c4 = (q & 7) * 4;
                int row = bm + r;
                pa[i] = (row < N_SRC)
                            ? *(const float4*)(A + (size_t)row * 256 + (kt + 1) * 32 + c4)
                            : make_float4(0.f, 0.f, 0.f, 0.f);
            }
            int n = tid >> 2, kc = (tid & 3) * 8;
            pb = *(const uint4*)(g_Bt + (size_t)(bn + n) * 256 + (kt + 1) * 32 + kc);
        }

        // two k16 sub-steps, operands via ldmatrix.x4
#pragma unroll
        for (int s = 0; s < 2; s++) {
            unsigned ah[2][4], al[2][4], bb[4][2];
#pragma unroll
            for (int ia = 0; ia < 2; ia++) {
                unsigned off = aoff + (ia * 640 + s * 16) * 2;
                ldsm4(ah[ia][0], ah[ia][1], ah[ia][2], ah[ia][3], sAh_b + off);
                ldsm4(al[ia][0], al[ia][1], al[ia][2], al[ia][3], sAl_b + off);
            }
#pragma unroll
            for (int p = 0; p < 2; p++) {
                unsigned off = boff + (p * 640 + s * 16) * 2;
                ldsm4(bb[2 * p][0], bb[2 * p][1], bb[2 * p + 1][0], bb[2 * p + 1][1],
                      sB_b + off);
            }
#pragma unroll
            for (int ia = 0; ia < 2; ia++)
#pragma unroll
                for (int ja = 0; ja < 4; ja++) {
                    mma16816h(c[ia][ja], ah[ia][0], ah[ia][1], ah[ia][2], ah[ia][3],
                              bb[ja][0], bb[ja][1]);
                    mma16816h(c[ia][ja], al[ia][0], al[ia][1], al[ia][2], al[ia][3],
                              bb[ja][0], bb[ja][1]);
                }
        }
        if (kt < 7) __syncthreads();
    }

    // epilogue 1: fp32 accumulators -> fp16 fs
    const int tq = lane >> 2, tr = lane & 3;
#pragma unroll
    for (int ia = 0; ia < 2; ia++) {
        int row0 = bm + wm * 32 + ia * 16 + tq;
#pragma unroll
        for (int ja = 0; ja < 4; ja++) {
            int col = bn + wn * 32 + ja * 8 + 2 * tr;
            if (row0 < N_SRC)
                *(__half2*)&g_fs[(size_t)row0 * 256 + col] =
                    __floats2half2_rn(c[ia][ja][0], c[ia][ja][1]);
            if (row0 + 8 < N_SRC)
                *(__half2*)&g_fs[(size_t)(row0 + 8) * 256 + col] =
                    __floats2half2_rn(c[ia][ja][2], c[ia][ja][3]);
        }
    }

    // epilogue 2: fused e_src — this warp's 32 cols = exactly one head
    {
        const int hd = (bn + wn * 32) >> 5;
        float rE[8];
#pragma unroll
        for (int ja = 0; ja < 4; ja++) {
            int col = bn + wn * 32 + ja * 8 + 2 * tr;
            rE[ja * 2]     = g_relE[col];
            rE[ja * 2 + 1] = g_relE[col + 1];
        }
#pragma unroll
        for (int ia = 0; ia < 2; ia++) {
            float p0 = 0.f, p8 = 0.f;
#pragma unroll
            for (int ja = 0; ja < 4; ja++) {
                p0 += c[ia][ja][0] * rE[ja * 2] + c[ia][ja][1] * rE[ja * 2 + 1];
                p8 += c[ia][ja][2] * rE[ja * 2] + c[ia][ja][3] * rE[ja * 2 + 1];
            }
            p0 += __shfl_xor_sync(~0u, p0, 1);
            p0 += __shfl_xor_sync(~0u, p0, 2);
            p8 += __shfl_xor_sync(~0u, p8, 1);
            p8 += __shfl_xor_sync(~0u, p8, 2);
            int row0 = bm + wm * 32 + ia * 16 + tq;
            if (tr == 0) {
                if (row0 < N_SRC) g_esrc[row0 * 8 + hd] = p0;
                if (row0 + 8 < N_SRC) g_esrc[(row0 + 8) * 8 + hd] = p8;
            }
        }
    }
}

// ---------------- 5. three-phase exclusive scan ---------------------------------
__global__ __launch_bounds__(256) void scanA_kernel() {
    __shared__ int sh[256];
    int t = threadIdx.x;
    int i = blockIdx.x * 256 + t;
    sh[t] = (i < N_DST) ? g_count[i] : 0;
    __syncthreads();
#pragma unroll
    for (int off = 128; off; off >>= 1) {
        if (t < off) sh[t] += sh[t + off];
        __syncthreads();
    }
    if (t == 0) g_part[blockIdx.x] = sh[0];
}

__global__ __launch_bounds__(256) void scanB_kernel() {
    __shared__ int sh[256];
    int t = threadIdx.x;
    int v = (t < NCHUNK) ? g_part[t] : 0;
    sh[t] = v;
    __syncthreads();
#pragma unroll
    for (int off = 1; off < 256; off <<= 1) {
        int x = (t >= off) ? sh[t - off] : 0;
        __syncthreads();
        sh[t] += x;
        __syncthreads();
    }
    if (t < NCHUNK) g_part[t] = sh[t] - v;
    if (t == 255) g_off[N_DST] = sh[255];
}

__global__ __launch_bounds__(256) void scanC_kernel() {
    __shared__ int sh[256];
    int t = threadIdx.x;
    int i = blockIdx.x * 256 + t;
    int v = (i < N_DST) ? g_count[i] : 0;
    sh[t] = v;
    __syncthreads();
#pragma unroll
    for (int off = 1; off < 256; off <<= 1) {
        int x = (t >= off) ? sh[t - off] : 0;
        __syncthreads();
        sh[t] += x;
        __syncthreads();
    }
    if (i < N_DST) {
        int excl = sh[t] - v + g_part[blockIdx.x];
        g_off[i] = excl;
        g_cursor[i] = excl;
    }
}

// ---------------- 6. scatter src ids into CSR slots ----------------------------
__global__ __launch_bounds__(256) void scatter_kernel(const int* __restrict__ src_idx,
                                                      const int* __restrict__ dst_idx) {
    int e = blockIdx.x * 256 + threadIdx.x;
    if (e >= NEDGE) return;
    int t = dst_idx[e];
    int p = atomicAdd(&g_cursor[t], 1);
    g_srcs[p] = src_idx[e];
}

// ---------------- 7. fused softmax + aggregation (R10 structure, fp16 fs) ------
__global__ __launch_bounds__(256) void edge_agg(float* __restrict__ out) {
    int warp = threadIdx.x >> 5, lane = threadIdx.x & 31;
    int dst = blockIdx.x * 8 + warp;
    if (dst >= N_DST) return;
    const int beg = g_off[dst], end = g_off[dst + 1];
    const int h = lane >> 2;
    const float ed = g_edst[dst * 8 + h];
    const int col = lane * 8;

    float dsum = 0.f;
    float acc0 = 0, acc1 = 0, acc2 = 0, acc3 = 0, acc4 = 0, acc5 = 0, acc6 = 0, acc7 = 0;

    int i = beg;
    for (; i + 4 <= end; i += 4) {
        int s0 = __ldg(&g_srcs[i]);
        int s1 = __ldg(&g_srcs[i + 1]);
        int s2 = __ldg(&g_srcs[i + 2]);
        int s3 = __ldg(&g_srcs[i + 3]);
        float e0 = __ldg(&g_esrc[s0 * 8 + h]);
        float e1 = __ldg(&g_esrc[s1 * 8 + h]);
        float e2 = __ldg(&g_esrc[s2 * 8 + h]);
        float e3 = __ldg(&g_esrc[s3 * 8 + h]);
        uint4 u0 = *(const uint4*)(g_fs + (size_t)s0 * 256 + col);
        uint4 u1 = *(const uint4*)(g_fs + (size_t)s1 * 256 + col);
        uint4 u2 = *(const uint4*)(g_fs + (size_t)s2 * 256 + col);
        uint4 u3 = *(const uint4*)(g_fs + (size_t)s3 * 256 + col);
        float v0 = e0 + ed; v0 = v0 > 0.f ? v0 : NEG * v0;
        float v1 = e1 + ed; v1 = v1 > 0.f ? v1 : NEG * v1;
        float v2 = e2 + ed; v2 = v2 > 0.f ? v2 : NEG * v2;
        float v3 = e3 + ed; v3 = v3 > 0.f ? v3 : NEG * v3;
        float a0 = __expf(v0), a1 = __expf(v1), a2 = __expf(v2), a3 = __expf(v3);
        dsum += (a0 + a1) + (a2 + a3);
#define ACC_EDGE(u, a)                                                        \
        {                                                                     \
            float2 p0 = __half22float2(*(const __half2*)&(u).x);              \
            float2 p1 = __half22float2(*(const __half2*)&(u).y);              \
            float2 p2 = __half22float2(*(const __half2*)&(u).z);              \
            float2 p3 = __half22float2(*(const __half2*)&(u).w);              \
            acc0 += (a) * p0.x; acc1 += (a) * p0.y;                           \
            acc2 += (a) * p1.x; acc3 += (a) * p1.y;                           \
            acc4 += (a) * p2.x; acc5 += (a) * p2.y;                           \
            acc6 += (a) * p3.x; acc7 += (a) * p3.y;                           \
        }
        ACC_EDGE(u0, a0)
        ACC_EDGE(u1, a1)
        ACC_EDGE(u2, a2)
        ACC_EDGE(u3, a3)
    }
    for (; i < end; i++) {
        int s = __ldg(&g_srcs[i]);
        float es = __ldg(&g_esrc[s * 8 + h]);
        float v = es + ed;
        v = v > 0.f ? v : NEG * v;
        float a = __expf(v);
        dsum += a;
        uint4 u = *(const uint4*)(g_fs + (size_t)s * 256 + col);
        ACC_EDGE(u, a)
    }
#undef ACC_EDGE
    const float dinv = 1.0f / dsum;
    float4* o = (float4*)(out + (size_t)dst * 256 + col);
    // fmaxf(NaN, 0) == 0 handles the empty-segment (0 * inf) case
    o[0] = make_float4(fmaxf(acc0 * dinv, 0.f), fmaxf(acc1 * dinv, 0.f),
                       fmaxf(acc2 * dinv, 0.f), fmaxf(acc3 * dinv, 0.f));
    o[1] = make_float4(fmaxf(acc4 * dinv, 0.f), fmaxf(acc5 * dinv, 0.f),
                       fmaxf(acc6 * dinv, 0.f), fmaxf(acc7 * dinv, 0.f));
}

// ---------------- launch --------------------------------------------------------
extern "C" void kernel_launch(void* const* d_in, const int* in_sizes, int n_in,
                              void* d_out, int out_size) {
    const float* feat_src = (const float*)d_in[0];
    const float* feat_dst = (const float*)d_in[1];
    const float* src_w    = (const float*)d_in[2];
    const float* dst_w    = (const float*)d_in[3];
    const float* rel_emb  = (const float*)d_in[4];
    const float* rel_w    = (const float*)d_in[5];
    const int*   src_idx  = (const int*)d_in[6];
    const int*   dst_idx  = (const int*)d_in[7];
    float* out = (float*)d_out;

    prep_kernel<<<64, 256>>>(rel_emb, rel_w, src_w, dst_w);
    gemv_dst<<<(N_DST + 7) / 8, 256>>>(feat_dst);
    hist_kernel<<<(NEDGE + 255) / 256, 256>>>(dst_idx);
    gemm_fp16<<<dim3(4, (N_SRC + 127) / 128), 256>>>(feat_src);   // profiled slot
    scanA_kernel<<<NCHUNK, 256>>>();
    scanB_kernel<<<1, 256>>>();
    scanC_kernel<<<NCHUNK, 256>>>();
    scatter_kernel<<<(NEDGE + 255) / 256, 256>>>(src_idx, dst_idx);
    edge_agg<<<(N_DST + 7) / 8, 256>>>(out);
}

// round 15
// speedup vs baseline: 1.3897x; 1.0348x over previous
#include <cuda_runtime.h>
#include <cuda_fp16.h>
#include <math_constants.h>
#include <cstdint>

#define N_SRC 50000
#define N_DST 50000
#define NEDGE 800000
#define D_IN  256
#define H     8
#define D     32
#define HD    256
#define NEG   0.2f
#define NCHUNK ((N_DST + 255) / 256)   // 196

// ---------------- scratch (device globals) ----------------------------------
__device__ __align__(16) __half g_fs[(size_t)N_SRC * HD];  // 25.6 MB fp16 fs
__device__ float g_esrc[N_SRC * H];
__device__ float g_edst[N_DST * H];
__device__ float g_wedst[H * D_IN];              // folded [h][k]
__device__ float g_relE[256];                    // relE[col] = rel[col/32][D+col%32]
__device__ int   g_count[N_DST];
__device__ int   g_off[N_DST + 1];
__device__ int   g_cursor[N_DST];
__device__ int   g_srcs[NEDGE];                  // CSR: src id per slot
__device__ int   g_part[NCHUNK];
__device__ __align__(16) __half g_Bt[256 * 256]; // src_w^T fp16 [n][k]

// ---------------- 1. prep: fold rel, zero counts, transpose B fp16, relE -------
__global__ void prep_kernel(const float* __restrict__ rel_emb,
                            const float* __restrict__ rel_w,
                            const float* __restrict__ src_w,
                            const float* __restrict__ dst_w) {
    int gi = blockIdx.x * blockDim.x + threadIdx.x;
    for (int i = gi; i < N_DST; i += gridDim.x * blockDim.x) g_count[i] = 0;

    for (int idx = gi; idx < 256 * 256; idx += gridDim.x * blockDim.x) {
        int k = idx >> 8, n = idx & 255;
        g_Bt[n * 256 + k] = __float2half_rn(src_w[idx]);
    }

    if (blockIdx.x == 0) {
        __shared__ float s_rel[H * 2 * D];  // 512
        int tid = threadIdx.x;
        for (int t = tid; t < 512; t += 256) {
            float s = 0.f;
            for (int r = 0; r < 64; r++) s += rel_emb[r] * rel_w[r * 512 + t];
            s_rel[t] = s;
        }
        __syncthreads();
        if (tid < 256) g_relE[tid] = s_rel[(tid >> 5) * 64 + 32 + (tid & 31)];
        for (int t = tid; t < H * D_IN; t += 256) {
            int h = t >> 8, k = t & 255;
            float s2 = 0.f;
#pragma unroll
            for (int d = 0; d < D; d++)
                s2 += dst_w[(size_t)k * 256 + h * 32 + d] * s_rel[h * 64 + d];
            g_wedst[h * 256 + k] = s2;
        }
    }
}

// ---------------- 2. e_dst GEMV (8 cols) ----------------------------------------
__global__ __launch_bounds__(256) void gemv_dst(const float* __restrict__ feat_dst) {
    __shared__ float sw[H * D_IN];
    for (int t = threadIdx.x; t < H * D_IN; t += 256) sw[t] = g_wedst[t];
    __syncthreads();
    int warp = threadIdx.x >> 5, lane = threadIdx.x & 31;
    int row = blockIdx.x * 8 + warp;
    if (row >= N_DST) return;
    float acc[8] = {0, 0, 0, 0, 0, 0, 0, 0};
    const float* fr = feat_dst + (size_t)row * 256;
    for (int k = lane; k < 256; k += 32) {
        float f = fr[k];
#pragma unroll
        for (int h = 0; h < 8; h++) acc[h] += f * sw[h * 256 + k];
    }
#pragma unroll
    for (int h = 0; h < 8; h++)
#pragma unroll
        for (int o = 16; o; o >>= 1) acc[h] += __shfl_xor_sync(~0u, acc[h], o);
    if (lane == 0) {
#pragma unroll
        for (int h = 0; h < 8; h++) g_edst[row * 8 + h] = acc[h];
    }
}

// ---------------- 3. degree histogram -----------------------------------------
__global__ __launch_bounds__(256) void hist_kernel(const int* __restrict__ dst_idx) {
    int e = blockIdx.x * 256 + threadIdx.x;
    if (e < NEDGE) atomicAdd(&g_count[dst_idx[e]], 1);
}

// ---------------- 4. fs = feat_src @ src_w  (single-plane fp16 A x fp16 B) -----
__device__ __forceinline__ void mma16816h(float* c, unsigned a0, unsigned a1,
                                          unsigned a2, unsigned a3,
                                          unsigned b0, unsigned b1) {
    asm("mma.sync.aligned.m16n8k16.row.col.f32.f16.f16.f32 "
        "{%0,%1,%2,%3},{%4,%5,%6,%7},{%8,%9},{%0,%1,%2,%3};"
        : "+f"(c[0]), "+f"(c[1]), "+f"(c[2]), "+f"(c[3])
        : "r"(a0), "r"(a1), "r"(a2), "r"(a3), "r"(b0), "r"(b1));
}
__device__ __forceinline__ void ldsm4(unsigned& r0, unsigned& r1, unsigned& r2,
                                      unsigned& r3, unsigned addr) {
    asm volatile("ldmatrix.sync.aligned.m8n8.x4.shared.b16 {%0,%1,%2,%3}, [%4];"
                 : "=r"(r0), "=r"(r1), "=r"(r2), "=r"(r3) : "r"(addr));
}

__global__ __launch_bounds__(256, 2) void gemm_fp16(const float* __restrict__ A) {
    __shared__ __align__(16) __half sA[128][40];   // [m][k]
    __shared__ __align__(16) __half sB[64][40];    // [n][k]

    const int tid = threadIdx.x;
    const int bm = blockIdx.y * 128;
    const int bn = blockIdx.x * 64;
    const int wid = tid >> 5, lane = tid & 31;
    const int wm = wid & 3, wn = wid >> 2;   // 4x2 warp grid, warp tile 32x32

    float c[2][4][4];
#pragma unroll
    for (int i = 0; i < 2; i++)
#pragma unroll
        for (int j = 0; j < 4; j++)
#pragma unroll
            for (int k = 0; k < 4; k++) c[i][j][k] = 0.f;

    float4 pa[4];
    uint4 pb;
#pragma unroll
    for (int i = 0; i < 4; i++) {
        int q = tid + 256 * i;
        int r = q >> 3, c4 = (q & 7) * 4;
        int row = bm + r;
        pa[i] = (row < N_SRC) ? *(const float4*)(A + (size_t)row * 256 + c4)
                              : make_float4(0.f, 0.f, 0.f, 0.f);
    }
    {
        int n = tid >> 2, kc = (tid & 3) * 8;
        pb = *(const uint4*)(g_Bt + (size_t)(bn + n) * 256 + kc);
    }

    const unsigned sA_b = (unsigned)__cvta_generic_to_shared(&sA[0][0]);
    const unsigned sB_b = (unsigned)__cvta_generic_to_shared(&sB[0][0]);
    const int l = lane;
    const unsigned aoff =
        (((wm * 32 + (l & 7) + ((l >> 3) & 1) * 8) * 40) + ((l >> 4) & 1) * 8) * 2;
    const unsigned boff =
        (((wn * 32 + (l & 7) + ((l >> 4) & 1) * 8) * 40) + ((l >> 3) & 1) * 8) * 2;

    for (int kt = 0; kt < 8; kt++) {
        // A: convert fp32 -> fp16 (single plane); B: plain 16B copy
#pragma unroll
        for (int i = 0; i < 4; i++) {
            int q = tid + 256 * i;
            int r = q >> 3, c4 = (q & 7) * 4;
            float4 v = pa[i];
            *(__half2*)&sA[r][c4] = __floats2half2_rn(v.x, v.y);
            *(__half2*)&sA[r][c4 + 2] = __floats2half2_rn(v.z, v.w);
        }
        {
            int n = tid >> 2, kc = (tid & 3) * 8;
            *(uint4*)&sB[n][kc] = pb;
        }
        __syncthreads();

        if (kt < 7) {
#pragma unroll
            for (int i = 0; i < 4; i++) {
                int q = tid + 256 * i;
                int r = q >> 3, c4 = (q & 7) * 4;
                int row = bm + r;
                pa[i] = (row < N_SRC)
                            ? *(const float4*)(A + (size_t)row * 256 + (kt + 1) * 32 + c4)
                            : make_float4(0.f, 0.f, 0.f, 0.f);
            }
            int n = tid >> 2, kc = (tid & 3) * 8;
            pb = *(const uint4*)(g_Bt + (size_t)(bn + n) * 256 + (kt + 1) * 32 + kc);
        }

        // two k16 sub-steps, operands via ldmatrix.x4
#pragma unroll
        for (int s = 0; s < 2; s++) {
            unsigned ah[2][4], bb[4][2];
#pragma unroll
            for (int ia = 0; ia < 2; ia++) {
                unsigned off = aoff + (ia * 640 + s * 16) * 2;
                ldsm4(ah[ia][0], ah[ia][1], ah[ia][2], ah[ia][3], sA_b + off);
            }
#pragma unroll
            for (int p = 0; p < 2; p++) {
                unsigned off = boff + (p * 640 + s * 16) * 2;
                ldsm4(bb[2 * p][0], bb[2 * p][1], bb[2 * p + 1][0], bb[2 * p + 1][1],
                      sB_b + off);
            }
#pragma unroll
            for (int ia = 0; ia < 2; ia++)
#pragma unroll
                for (int ja = 0; ja < 4; ja++)
                    mma16816h(c[ia][ja], ah[ia][0], ah[ia][1], ah[ia][2], ah[ia][3],
                              bb[ja][0], bb[ja][1]);
        }
        if (kt < 7) __syncthreads();
    }

    // epilogue 1: fp32 accumulators -> fp16 fs
    const int tq = lane >> 2, tr = lane & 3;
#pragma unroll
    for (int ia = 0; ia < 2; ia++) {
        int row0 = bm + wm * 32 + ia * 16 + tq;
#pragma unroll
        for (int ja = 0; ja < 4; ja++) {
            int col = bn + wn * 32 + ja * 8 + 2 * tr;
            if (row0 < N_SRC)
                *(__half2*)&g_fs[(size_t)row0 * 256 + col] =
                    __floats2half2_rn(c[ia][ja][0], c[ia][ja][1]);
            if (row0 + 8 < N_SRC)
                *(__half2*)&g_fs[(size_t)(row0 + 8) * 256 + col] =
                    __floats2half2_rn(c[ia][ja][2], c[ia][ja][3]);
        }
    }

    // epilogue 2: fused e_src — this warp's 32 cols = exactly one head
    {
        const int hd = (bn + wn * 32) >> 5;
        float rE[8];
#pragma unroll
        for (int ja = 0; ja < 4; ja++) {
            int col = bn + wn * 32 + ja * 8 + 2 * tr;
            rE[ja * 2]     = g_relE[col];
            rE[ja * 2 + 1] = g_relE[col + 1];
        }
#pragma unroll
        for (int ia = 0; ia < 2; ia++) {
            float p0 = 0.f, p8 = 0.f;
#pragma unroll
            for (int ja = 0; ja < 4; ja++) {
                p0 += c[ia][ja][0] * rE[ja * 2] + c[ia][ja][1] * rE[ja * 2 + 1];
                p8 += c[ia][ja][2] * rE[ja * 2] + c[ia][ja][3] * rE[ja * 2 + 1];
            }
            p0 += __shfl_xor_sync(~0u, p0, 1);
            p0 += __shfl_xor_sync(~0u, p0, 2);
            p8 += __shfl_xor_sync(~0u, p8, 1);
            p8 += __shfl_xor_sync(~0u, p8, 2);
            int row0 = bm + wm * 32 + ia * 16 + tq;
            if (tr == 0) {
                if (row0 < N_SRC) g_esrc[row0 * 8 + hd] = p0;
                if (row0 + 8 < N_SRC) g_esrc[(row0 + 8) * 8 + hd] = p8;
            }
        }
    }
}

// ---------------- 5. three-phase exclusive scan ---------------------------------
__global__ __launch_bounds__(256) void scanA_kernel() {
    __shared__ int sh[256];
    int t = threadIdx.x;
    int i = blockIdx.x * 256 + t;
    sh[t] = (i < N_DST) ? g_count[i] : 0;
    __syncthreads();
#pragma unroll
    for (int off = 128; off; off >>= 1) {
        if (t < off) sh[t] += sh[t + off];
        __syncthreads();
    }
    if (t == 0) g_part[blockIdx.x] = sh[0];
}

__global__ __launch_bounds__(256) void scanB_kernel() {
    __shared__ int sh[256];
    int t = threadIdx.x;
    int v = (t < NCHUNK) ? g_part[t] : 0;
    sh[t] = v;
    __syncthreads();
#pragma unroll
    for (int off = 1; off < 256; off <<= 1) {
        int x = (t >= off) ? sh[t - off] : 0;
        __syncthreads();
        sh[t] += x;
        __syncthreads();
    }
    if (t < NCHUNK) g_part[t] = sh[t] - v;
    if (t == 255) g_off[N_DST] = sh[255];
}

__global__ __launch_bounds__(256) void scanC_kernel() {
    __shared__ int sh[256];
    int t = threadIdx.x;
    int i = blockIdx.x * 256 + t;
    int v = (i < N_DST) ? g_count[i] : 0;
    sh[t] = v;
    __syncthreads();
#pragma unroll
    for (int off = 1; off < 256; off <<= 1) {
        int x = (t >= off) ? sh[t - off] : 0;
        __syncthreads();
        sh[t] += x;
        __syncthreads();
    }
    if (i < N_DST) {
        int excl = sh[t] - v + g_part[blockIdx.x];
        g_off[i] = excl;
        g_cursor[i] = excl;
    }
}

// ---------------- 6. scatter src ids into CSR slots ----------------------------
__global__ __launch_bounds__(256) void scatter_kernel(const int* __restrict__ src_idx,
                                                      const int* __restrict__ dst_idx) {
    int e = blockIdx.x * 256 + threadIdx.x;
    if (e >= NEDGE) return;
    int t = dst_idx[e];
    int p = atomicAdd(&g_cursor[t], 1);
    g_srcs[p] = src_idx[e];
}

// ---------------- 7. fused softmax + aggregation (R10 structure, fp16 fs) ------
__global__ __launch_bounds__(256) void edge_agg(float* __restrict__ out) {
    int warp = threadIdx.x >> 5, lane = threadIdx.x & 31;
    int dst = blockIdx.x * 8 + warp;
    if (dst >= N_DST) return;
    const int beg = g_off[dst], end = g_off[dst + 1];
    const int h = lane >> 2;
    const float ed = g_edst[dst * 8 + h];
    const int col = lane * 8;

    float dsum = 0.f;
    float acc0 = 0, acc1 = 0, acc2 = 0, acc3 = 0, acc4 = 0, acc5 = 0, acc6 = 0, acc7 = 0;

    int i = beg;
    for (; i + 4 <= end; i += 4) {
        int s0 = __ldg(&g_srcs[i]);
        int s1 = __ldg(&g_srcs[i + 1]);
        int s2 = __ldg(&g_srcs[i + 2]);
        int s3 = __ldg(&g_srcs[i + 3]);
        float e0 = __ldg(&g_esrc[s0 * 8 + h]);
        float e1 = __ldg(&g_esrc[s1 * 8 + h]);
        float e2 = __ldg(&g_esrc[s2 * 8 + h]);
        float e3 = __ldg(&g_esrc[s3 * 8 + h]);
        uint4 u0 = *(const uint4*)(g_fs + (size_t)s0 * 256 + col);
        uint4 u1 = *(const uint4*)(g_fs + (size_t)s1 * 256 + col);
        uint4 u2 = *(const uint4*)(g_fs + (size_t)s2 * 256 + col);
        uint4 u3 = *(const uint4*)(g_fs + (size_t)s3 * 256 + col);
        float v0 = e0 + ed; v0 = v0 > 0.f ? v0 : NEG * v0;
        float v1 = e1 + ed; v1 = v1 > 0.f ? v1 : NEG * v1;
        float v2 = e2 + ed; v2 = v2 > 0.f ? v2 : NEG * v2;
        float v3 = e3 + ed; v3 = v3 > 0.f ? v3 : NEG * v3;
        float a0 = __expf(v0), a1 = __expf(v1), a2 = __expf(v2), a3 = __expf(v3);
        dsum += (a0 + a1) + (a2 + a3);
#define ACC_EDGE(u, a)                                                        \
        {                                                                     \
            float2 p0 = __half22float2(*(const __half2*)&(u).x);              \
            float2 p1 = __half22float2(*(const __half2*)&(u).y);              \
            float2 p2 = __half22float2(*(const __half2*)&(u).z);              \
            float2 p3 = __half22float2(*(const __half2*)&(u).w);              \
            acc0 += (a) * p0.x; acc1 += (a) * p0.y;                           \
            acc2 += (a) * p1.x; acc3 += (a) * p1.y;                           \
            acc4 += (a) * p2.x; acc5 += (a) * p2.y;                           \
            acc6 += (a) * p3.x; acc7 += (a) * p3.y;                           \
        }
        ACC_EDGE(u0, a0)
        ACC_EDGE(u1, a1)
        ACC_EDGE(u2, a2)
        ACC_EDGE(u3, a3)
    }
    for (; i < end; i++) {
        int s = __ldg(&g_srcs[i]);
        float es = __ldg(&g_esrc[s * 8 + h]);
        float v = es + ed;
        v = v > 0.f ? v : NEG * v;
        float a = __expf(v);
        dsum += a;
        uint4 u = *(const uint4*)(g_fs + (size_t)s * 256 + col);
        ACC_EDGE(u, a)
    }
#undef ACC_EDGE
    const float dinv = 1.0f / dsum;
    float4* o = (float4*)(out + (size_t)dst * 256 + col);
    // fmaxf(NaN, 0) == 0 handles the empty-segment (0 * inf) case
    o[0] = make_float4(fmaxf(acc0 * dinv, 0.f), fmaxf(acc1 * dinv, 0.f),
                       fmaxf(acc2 * dinv, 0.f), fmaxf(acc3 * dinv, 0.f));
    o[1] = make_float4(fmaxf(acc4 * dinv, 0.f), fmaxf(acc5 * dinv, 0.f),
                       fmaxf(acc6 * dinv, 0.f), fmaxf(acc7 * dinv, 0.f));
}

// ---------------- launch --------------------------------------------------------
extern "C" void kernel_launch(void* const* d_in, const int* in_sizes, int n_in,
                              void* d_out, int out_size) {
    const float* feat_src = (const float*)d_in[0];
    const float* feat_dst = (const float*)d_in[1];
    const float* src_w    = (const float*)d_in[2];
    const float* dst_w    = (const float*)d_in[3];
    const float* rel_emb  = (const float*)d_in[4];
    const float* rel_w    = (const float*)d_in[5];
    const int*   src_idx  = (const int*)d_in[6];
    const int*   dst_idx  = (const int*)d_in[7];
    float* out = (float*)d_out;

    prep_kernel<<<64, 256>>>(rel_emb, rel_w, src_w, dst_w);
    gemv_dst<<<(N_DST + 7) / 8, 256>>>(feat_dst);
    hist_kernel<<<(NEDGE + 255) / 256, 256>>>(dst_idx);
    gemm_fp16<<<dim3(4, (N_SRC + 127) / 128), 256>>>(feat_src);   // profiled slot
    scanA_kernel<<<NCHUNK, 256>>>();
    scanB_kernel<<<1, 256>>>();
    scanC_kernel<<<NCHUNK, 256>>>();
    scatter_kernel<<<(NEDGE + 255) / 256, 256>>>(src_idx, dst_idx);
    edge_agg<<<(N_DST + 7) / 8, 256>>>(out);
}

// round 16
// speedup vs baseline: 1.4764x; 1.0624x over previous
#include <cuda_runtime.h>
#include <cuda_fp16.h>
#include <math_constants.h>
#include <cstdint>

#define N_SRC 50000
#define N_DST 50000
#define NEDGE 800000
#define D_IN  256
#define H     8
#define D     32
#define HD    256
#define NEG   0.2f
#define NCHUNK ((N_DST + 255) / 256)   // 196

// ---------------- scratch (device globals) ----------------------------------
__device__ __align__(16) __half g_fs[(size_t)N_SRC * HD];  // 25.6 MB fp16 fs
__device__ float g_esrc[N_SRC * H];
__device__ float g_edst[N_DST * H];
__device__ float g_wedst[H * D_IN];              // folded [h][k]
__device__ float g_relE[256];                    // relE[col] = rel[col/32][D+col%32]
__device__ int   g_count[N_DST];
__device__ int   g_off[N_DST + 1];
__device__ int   g_cursor[N_DST];
__device__ int   g_srcs[NEDGE];                  // CSR: src id per slot
__device__ int   g_part[NCHUNK];
__device__ __align__(16) __half g_Bt[256 * 256]; // src_w^T fp16 [n][k]

// ---------------- 1. prep: fold rel, zero counts, transpose B fp16, relE -------
__global__ void prep_kernel(const float* __restrict__ rel_emb,
                            const float* __restrict__ rel_w,
                            const float* __restrict__ src_w,
                            const float* __restrict__ dst_w) {
    int gi = blockIdx.x * blockDim.x + threadIdx.x;
    for (int i = gi; i < N_DST; i += gridDim.x * blockDim.x) g_count[i] = 0;

    for (int idx = gi; idx < 256 * 256; idx += gridDim.x * blockDim.x) {
        int k = idx >> 8, n = idx & 255;
        g_Bt[n * 256 + k] = __float2half_rn(src_w[idx]);
    }

    if (blockIdx.x == 0) {
        __shared__ float s_rel[H * 2 * D];  // 512
        int tid = threadIdx.x;
        for (int t = tid; t < 512; t += 256) {
            float s = 0.f;
            for (int r = 0; r < 64; r++) s += rel_emb[r] * rel_w[r * 512 + t];
            s_rel[t] = s;
        }
        __syncthreads();
        if (tid < 256) g_relE[tid] = s_rel[(tid >> 5) * 64 + 32 + (tid & 31)];
        for (int t = tid; t < H * D_IN; t += 256) {
            int h = t >> 8, k = t & 255;
            float s2 = 0.f;
#pragma unroll
            for (int d = 0; d < D; d++)
                s2 += dst_w[(size_t)k * 256 + h * 32 + d] * s_rel[h * 64 + d];
            g_wedst[h * 256 + k] = s2;
        }
    }
}

// ---------------- 2. e_dst GEMV (8 cols) ----------------------------------------
__global__ __launch_bounds__(256) void gemv_dst(const float* __restrict__ feat_dst) {
    __shared__ float sw[H * D_IN];
    for (int t = threadIdx.x; t < H * D_IN; t += 256) sw[t] = g_wedst[t];
    __syncthreads();
    int warp = threadIdx.x >> 5, lane = threadIdx.x & 31;
    int row = blockIdx.x * 8 + warp;
    if (row >= N_DST) return;
    float acc[8] = {0, 0, 0, 0, 0, 0, 0, 0};
    const float* fr = feat_dst + (size_t)row * 256;
    for (int k = lane; k < 256; k += 32) {
        float f = fr[k];
#pragma unroll
        for (int h = 0; h < 8; h++) acc[h] += f * sw[h * 256 + k];
    }
#pragma unroll
    for (int h = 0; h < 8; h++)
#pragma unroll
        for (int o = 16; o; o >>= 1) acc[h] += __shfl_xor_sync(~0u, acc[h], o);
    if (lane == 0) {
#pragma unroll
        for (int h = 0; h < 8; h++) g_edst[row * 8 + h] = acc[h];
    }
}

// ---------------- 3. degree histogram -----------------------------------------
__global__ __launch_bounds__(256) void hist_kernel(const int* __restrict__ dst_idx) {
    int e = blockIdx.x * 256 + threadIdx.x;
    if (e < NEDGE) atomicAdd(&g_count[dst_idx[e]], 1);
}

// ---------------- 4. fs = feat_src @ src_w  (single-plane fp16 A x fp16 B) -----
__device__ __forceinline__ void mma16816h(float* c, unsigned a0, unsigned a1,
                                          unsigned a2, unsigned a3,
                                          unsigned b0, unsigned b1) {
    asm("mma.sync.aligned.m16n8k16.row.col.f32.f16.f16.f32 "
        "{%0,%1,%2,%3},{%4,%5,%6,%7},{%8,%9},{%0,%1,%2,%3};"
        : "+f"(c[0]), "+f"(c[1]), "+f"(c[2]), "+f"(c[3])
        : "r"(a0), "r"(a1), "r"(a2), "r"(a3), "r"(b0), "r"(b1));
}
__device__ __forceinline__ void ldsm4(unsigned& r0, unsigned& r1, unsigned& r2,
                                      unsigned& r3, unsigned addr) {
    asm volatile("ldmatrix.sync.aligned.m8n8.x4.shared.b16 {%0,%1,%2,%3}, [%4];"
                 : "=r"(r0), "=r"(r1), "=r"(r2), "=r"(r3) : "r"(addr));
}

__global__ __launch_bounds__(256, 2) void gemm_fp16(const float* __restrict__ A) {
    __shared__ __align__(16) __half sA[128][40];   // [m][k]
    __shared__ __align__(16) __half sB[64][40];    // [n][k]

    const int tid = threadIdx.x;
    const int bm = blockIdx.y * 128;
    const int bn = blockIdx.x * 64;
    const int wid = tid >> 5, lane = tid & 31;
    const int wm = wid & 3, wn = wid >> 2;   // 4x2 warp grid, warp tile 32x32

    float c[2][4][4];
#pragma unroll
    for (int i = 0; i < 2; i++)
#pragma unroll
        for (int j = 0; j < 4; j++)
#pragma unroll
            for (int k = 0; k < 4; k++) c[i][j][k] = 0.f;

    float4 pa[4];
    uint4 pb;
#pragma unroll
    for (int i = 0; i < 4; i++) {
        int q = tid + 256 * i;
        int r = q >> 3, c4 = (q & 7) * 4;
        int row = bm + r;
        pa[i] = (row < N_SRC) ? *(const float4*)(A + (size_t)row * 256 + c4)
                              : make_float4(0.f, 0.f, 0.f, 0.f);
    }
    {
        int n = tid >> 2, kc = (tid & 3) * 8;
        pb = *(const uint4*)(g_Bt + (size_t)(bn + n) * 256 + kc);
    }

    const unsigned sA_b = (unsigned)__cvta_generic_to_shared(&sA[0][0]);
    const unsigned sB_b = (unsigned)__cvta_generic_to_shared(&sB[0][0]);
    const int l = lane;
    const unsigned aoff =
        (((wm * 32 + (l & 7) + ((l >> 3) & 1) * 8) * 40) + ((l >> 4) & 1) * 8) * 2;
    const unsigned boff =
        (((wn * 32 + (l & 7) + ((l >> 4) & 1) * 8) * 40) + ((l >> 3) & 1) * 8) * 2;

    for (int kt = 0; kt < 8; kt++) {
        // A: convert fp32 -> fp16 (single plane); B: plain 16B copy
#pragma unroll
        for (int i = 0; i < 4; i++) {
            int q = tid + 256 * i;
            int r = q >> 3, c4 = (q & 7) * 4;
            float4 v = pa[i];
            *(__half2*)&sA[r][c4] = __floats2half2_rn(v.x, v.y);
            *(__half2*)&sA[r][c4 + 2] = __floats2half2_rn(v.z, v.w);
        }
        {
            int n = tid >> 2, kc = (tid & 3) * 8;
            *(uint4*)&sB[n][kc] = pb;
        }
        __syncthreads();

        if (kt < 7) {
#pragma unroll
            for (int i = 0; i < 4; i++) {
                int q = tid + 256 * i;
                int r = q >> 3, c4 = (q & 7) * 4;
                int row = bm + r;
                pa[i] = (row < N_SRC)
                            ? *(const float4*)(A + (size_t)row * 256 + (kt + 1) * 32 + c4)
                            : make_float4(0.f, 0.f, 0.f, 0.f);
            }
            int n = tid >> 2, kc = (tid & 3) * 8;
            pb = *(const uint4*)(g_Bt + (size_t)(bn + n) * 256 + (kt + 1) * 32 + kc);
        }

        // two k16 sub-steps, operands via ldmatrix.x4
#pragma unroll
        for (int s = 0; s < 2; s++) {
            unsigned ah[2][4], bb[4][2];
#pragma unroll
            for (int ia = 0; ia < 2; ia++) {
                unsigned off = aoff + (ia * 640 + s * 16) * 2;
                ldsm4(ah[ia][0], ah[ia][1], ah[ia][2], ah[ia][3], sA_b + off);
            }
#pragma unroll
            for (int p = 0; p < 2; p++) {
                unsigned off = boff + (p * 640 + s * 16) * 2;
                ldsm4(bb[2 * p][0], bb[2 * p][1], bb[2 * p + 1][0], bb[2 * p + 1][1],
                      sB_b + off);
            }
#pragma unroll
            for (int ia = 0; ia < 2; ia++)
#pragma unroll
                for (int ja = 0; ja < 4; ja++)
                    mma16816h(c[ia][ja], ah[ia][0], ah[ia][1], ah[ia][2], ah[ia][3],
                              bb[ja][0], bb[ja][1]);
        }
        if (kt < 7) __syncthreads();
    }

    // epilogue 1: fp32 accumulators -> fp16 fs
    const int tq = lane >> 2, tr = lane & 3;
#pragma unroll
    for (int ia = 0; ia < 2; ia++) {
        int row0 = bm + wm * 32 + ia * 16 + tq;
#pragma unroll
        for (int ja = 0; ja < 4; ja++) {
            int col = bn + wn * 32 + ja * 8 + 2 * tr;
            if (row0 < N_SRC)
                *(__half2*)&g_fs[(size_t)row0 * 256 + col] =
                    __floats2half2_rn(c[ia][ja][0], c[ia][ja][1]);
            if (row0 + 8 < N_SRC)
                *(__half2*)&g_fs[(size_t)(row0 + 8) * 256 + col] =
                    __floats2half2_rn(c[ia][ja][2], c[ia][ja][3]);
        }
    }

    // epilogue 2: fused e_src — this warp's 32 cols = exactly one head
    {
        const int hd = (bn + wn * 32) >> 5;
        float rE[8];
#pragma unroll
        for (int ja = 0; ja < 4; ja++) {
            int col = bn + wn * 32 + ja * 8 + 2 * tr;
            rE[ja * 2]     = g_relE[col];
            rE[ja * 2 + 1] = g_relE[col + 1];
        }
#pragma unroll
        for (int ia = 0; ia < 2; ia++) {
            float p0 = 0.f, p8 = 0.f;
#pragma unroll
            for (int ja = 0; ja < 4; ja++) {
                p0 += c[ia][ja][0] * rE[ja * 2] + c[ia][ja][1] * rE[ja * 2 + 1];
                p8 += c[ia][ja][2] * rE[ja * 2] + c[ia][ja][3] * rE[ja * 2 + 1];
            }
            p0 += __shfl_xor_sync(~0u, p0, 1);
            p0 += __shfl_xor_sync(~0u, p0, 2);
            p8 += __shfl_xor_sync(~0u, p8, 1);
            p8 += __shfl_xor_sync(~0u, p8, 2);
            int row0 = bm + wm * 32 + ia * 16 + tq;
            if (tr == 0) {
                if (row0 < N_SRC) g_esrc[row0 * 8 + hd] = p0;
                if (row0 + 8 < N_SRC) g_esrc[(row0 + 8) * 8 + hd] = p8;
            }
        }
    }
}

// ---------------- 5. three-phase exclusive scan ---------------------------------
__global__ __launch_bounds__(256) void scanA_kernel() {
    __shared__ int sh[256];
    int t = threadIdx.x;
    int i = blockIdx.x * 256 + t;
    sh[t] = (i < N_DST) ? g_count[i] : 0;
    __syncthreads();
#pragma unroll
    for (int off = 128; off; off >>= 1) {
        if (t < off) sh[t] += sh[t + off];
        __syncthreads();
    }
    if (t == 0) g_part[blockIdx.x] = sh[0];
}

__global__ __launch_bounds__(256) void scanB_kernel() {
    __shared__ int sh[256];
    int t = threadIdx.x;
    int v = (t < NCHUNK) ? g_part[t] : 0;
    sh[t] = v;
    __syncthreads();
#pragma unroll
    for (int off = 1; off < 256; off <<= 1) {
        int x = (t >= off) ? sh[t - off] : 0;
        __syncthreads();
        sh[t] += x;
        __syncthreads();
    }
    if (t < NCHUNK) g_part[t] = sh[t] - v;
    if (t == 255) g_off[N_DST] = sh[255];
}

__global__ __launch_bounds__(256) void scanC_kernel() {
    __shared__ int sh[256];
    int t = threadIdx.x;
    int i = blockIdx.x * 256 + t;
    int v = (i < N_DST) ? g_count[i] : 0;
    sh[t] = v;
    __syncthreads();
#pragma unroll
    for (int off = 1; off < 256; off <<= 1) {
        int x = (t >= off) ? sh[t - off] : 0;
        __syncthreads();
        sh[t] += x;
        __syncthreads();
    }
    if (i < N_DST) {
        int excl = sh[t] - v + g_part[blockIdx.x];
        g_off[i] = excl;
        g_cursor[i] = excl;
    }
}

// ---------------- 6. scatter src ids into CSR slots ----------------------------
__global__ __launch_bounds__(256) void scatter_kernel(const int* __restrict__ src_idx,
                                                      const int* __restrict__ dst_idx) {
    int e = blockIdx.x * 256 + threadIdx.x;
    if (e >= NEDGE) return;
    int t = dst_idx[e];
    int p = atomicAdd(&g_cursor[t], 1);
    g_srcs[p] = src_idx[e];
}

// ---------------- 7. fused softmax + aggregation (R10 structure, fp16 fs) ------
__global__ __launch_bounds__(256) void edge_agg(float* __restrict__ out) {
    int warp = threadIdx.x >> 5, lane = threadIdx.x & 31;
    int dst = blockIdx.x * 8 + warp;
    if (dst >= N_DST) return;
    const int beg = g_off[dst], end = g_off[dst + 1];
    const int h = lane >> 2;
    const float ed = g_edst[dst * 8 + h];
    const int col = lane * 8;

    float dsum = 0.f;
    float acc0 = 0, acc1 = 0, acc2 = 0, acc3 = 0, acc4 = 0, acc5 = 0, acc6 = 0, acc7 = 0;

    int i = beg;
    for (; i + 4 <= end; i += 4) {
        int s0 = __ldg(&g_srcs[i]);
        int s1 = __ldg(&g_srcs[i + 1]);
        int s2 = __ldg(&g_srcs[i + 2]);
        int s3 = __ldg(&g_srcs[i + 3]);
        float e0 = __ldg(&g_esrc[s0 * 8 + h]);
        float e1 = __ldg(&g_esrc[s1 * 8 + h]);
        float e2 = __ldg(&g_esrc[s2 * 8 + h]);
        float e3 = __ldg(&g_esrc[s3 * 8 + h]);
        uint4 u0 = *(const uint4*)(g_fs + (size_t)s0 * 256 + col);
        uint4 u1 = *(const uint4*)(g_fs + (size_t)s1 * 256 + col);
        uint4 u2 = *(const uint4*)(g_fs + (size_t)s2 * 256 + col);
        uint4 u3 = *(const uint4*)(g_fs + (size_t)s3 * 256 + col);
        float v0 = e0 + ed; v0 = v0 > 0.f ? v0 : NEG * v0;
        float v1 = e1 + ed; v1 = v1 > 0.f ? v1 : NEG * v1;
        float v2 = e2 + ed; v2 = v2 > 0.f ? v2 : NEG * v2;
        float v3 = e3 + ed; v3 = v3 > 0.f ? v3 : NEG * v3;
        float a0 = __expf(v0), a1 = __expf(v1), a2 = __expf(v2), a3 = __expf(v3);
        dsum += (a0 + a1) + (a2 + a3);
#define ACC_EDGE(u, a)                                                        \
        {                                                                     \
            float2 p0 = __half22float2(*(const __half2*)&(u).x);              \
            float2 p1 = __half22float2(*(const __half2*)&(u).y);              \
            float2 p2 = __half22float2(*(const __half2*)&(u).z);              \
            float2 p3 = __half22float2(*(const __half2*)&(u).w);              \
            acc0 += (a) * p0.x; acc1 += (a) * p0.y;                           \
            acc2 += (a) * p1.x; acc3 += (a) * p1.y;                           \
            acc4 += (a) * p2.x; acc5 += (a) * p2.y;                           \
            acc6 += (a) * p3.x; acc7 += (a) * p3.y;                           \
        }
        ACC_EDGE(u0, a0)
        ACC_EDGE(u1, a1)
        ACC_EDGE(u2, a2)
        ACC_EDGE(u3, a3)
    }
    for (; i < end; i++) {
        int s = __ldg(&g_srcs[i]);
        float es = __ldg(&g_esrc[s * 8 + h]);
        float v = es + ed;
        v = v > 0.f ? v : NEG * v;
        float a = __expf(v);
        dsum += a;
        uint4 u = *(const uint4*)(g_fs + (size_t)s * 256 + col);
        ACC_EDGE(u, a)
    }
#undef ACC_EDGE
    const float dinv = 1.0f / dsum;
    float4* o = (float4*)(out + (size_t)dst * 256 + col);
    // fmaxf(NaN, 0) == 0 handles the empty-segment (0 * inf) case
    o[0] = make_float4(fmaxf(acc0 * dinv, 0.f), fmaxf(acc1 * dinv, 0.f),
                       fmaxf(acc2 * dinv, 0.f), fmaxf(acc3 * dinv, 0.f));
    o[1] = make_float4(fmaxf(acc4 * dinv, 0.f), fmaxf(acc5 * dinv, 0.f),
                       fmaxf(acc6 * dinv, 0.f), fmaxf(acc7 * dinv, 0.f));
}

// ---------------- launch: fork GEMM branch || CSR branch -------------------------
extern "C" void kernel_launch(void* const* d_in, const int* in_sizes, int n_in,
                              void* d_out, int out_size) {
    const float* feat_src = (const float*)d_in[0];
    const float* feat_dst = (const float*)d_in[1];
    const float* src_w    = (const float*)d_in[2];
    const float* dst_w    = (const float*)d_in[3];
    const float* rel_emb  = (const float*)d_in[4];
    const float* rel_w    = (const float*)d_in[5];
    const int*   src_idx  = (const int*)d_in[6];
    const int*   dst_idx  = (const int*)d_in[7];
    float* out = (float*)d_out;

    // one-time handles (created on the first, non-captured correctness call)
    static cudaStream_t s1 = nullptr;
    static cudaEvent_t e_prep = nullptr, e_csr = nullptr;
    if (!s1) {
        cudaStreamCreateWithFlags(&s1, cudaStreamNonBlocking);
        cudaEventCreateWithFlags(&e_prep, cudaEventDisableTiming);
        cudaEventCreateWithFlags(&e_csr, cudaEventDisableTiming);
    }

    prep_kernel<<<64, 256>>>(rel_emb, rel_w, src_w, dst_w);
    cudaEventRecord(e_prep, 0);

    // CSR branch on s1 (DRAM/atomic-bound)
    cudaStreamWaitEvent(s1, e_prep, 0);
    gemv_dst<<<(N_DST + 7) / 8, 256, 0, s1>>>(feat_dst);
    hist_kernel<<<(NEDGE + 255) / 256, 256, 0, s1>>>(dst_idx);
    scanA_kernel<<<NCHUNK, 256, 0, s1>>>();
    scanB_kernel<<<1, 256, 0, s1>>>();
    scanC_kernel<<<NCHUNK, 256, 0, s1>>>();
    scatter_kernel<<<(NEDGE + 255) / 256, 256, 0, s1>>>(src_idx, dst_idx);
    cudaEventRecord(e_csr, s1);

    // GEMM branch on the default stream (tensor/L1-bound) — runs concurrently
    gemm_fp16<<<dim3(4, (N_SRC + 127) / 128), 256>>>(feat_src);

    // join, then aggregate
    cudaStreamWaitEvent(0, e_csr, 0);
    edge_agg<<<(N_DST + 7) / 8, 256>>>(out);
}

// round 17
// speedup vs baseline: 1.4933x; 1.0115x over previous
#include <cuda_runtime.h>
#include <cuda_fp16.h>
#include <math_constants.h>
#include <cstdint>

#define N_SRC 50000
#define N_DST 50000
#define NEDGE 800000
#define D_IN  256
#define H     8
#define D     32
#define HD    256
#define NEG   0.2f
#define NCHUNK ((N_DST + 255) / 256)   // 196

// ---------------- scratch (device globals) ----------------------------------
__device__ __align__(16) __half g_fs[(size_t)N_SRC * HD];  // 25.6 MB fp16 fs
__device__ float g_esrc[N_SRC * H];
__device__ float g_edst[N_DST * H];
__device__ float g_wedst[H * D_IN];              // folded [h][k]
__device__ float g_relE[256];                    // relE[col] = rel[col/32][D+col%32]
__device__ int   g_count[N_DST];                 // zero at start; scanC re-zeroes
__device__ int   g_off[N_DST + 1];
__device__ int   g_cursor[N_DST];
__device__ int   g_srcs[NEDGE];                  // CSR: src id per slot
__device__ int   g_part[NCHUNK];
__device__ __align__(16) __half g_Bt[256 * 256]; // src_w^T fp16 [n][k]

// ---------------- 1. prep + fused histogram ------------------------------------
// g_count is zero on entry (static init on first call; scanC re-zeroes on every
// pass), so the histogram can run concurrently with the rest of prep.
__global__ void prep_kernel(const float* __restrict__ rel_emb,
                            const float* __restrict__ rel_w,
                            const float* __restrict__ src_w,
                            const float* __restrict__ dst_w,
                            const int* __restrict__ dst_idx) {
    int gi = blockIdx.x * blockDim.x + threadIdx.x;
    int gs = gridDim.x * blockDim.x;

    // degree histogram (fused)
    for (int e = gi; e < NEDGE; e += gs) atomicAdd(&g_count[dst_idx[e]], 1);

    // B = src_w [k][n] -> transposed fp16 [n][k]
    for (int idx = gi; idx < 256 * 256; idx += gs) {
        int k = idx >> 8, n = idx & 255;
        g_Bt[n * 256 + k] = __float2half_rn(src_w[idx]);
    }

    if (blockIdx.x == 0) {
        __shared__ float s_rel[H * 2 * D];  // 512
        int tid = threadIdx.x;
        for (int t = tid; t < 512; t += 256) {
            float s = 0.f;
            for (int r = 0; r < 64; r++) s += rel_emb[r] * rel_w[r * 512 + t];
            s_rel[t] = s;
        }
        __syncthreads();
        if (tid < 256) g_relE[tid] = s_rel[(tid >> 5) * 64 + 32 + (tid & 31)];
        for (int t = tid; t < H * D_IN; t += 256) {
            int h = t >> 8, k = t & 255;
            float s2 = 0.f;
#pragma unroll
            for (int d = 0; d < D; d++)
                s2 += dst_w[(size_t)k * 256 + h * 32 + d] * s_rel[h * 64 + d];
            g_wedst[h * 256 + k] = s2;
        }
    }
}

// ---------------- 2. e_dst GEMV (8 cols) ----------------------------------------
__global__ __launch_bounds__(256) void gemv_dst(const float* __restrict__ feat_dst) {
    __shared__ float sw[H * D_IN];
    for (int t = threadIdx.x; t < H * D_IN; t += 256) sw[t] = g_wedst[t];
    __syncthreads();
    int warp = threadIdx.x >> 5, lane = threadIdx.x & 31;
    int row = blockIdx.x * 8 + warp;
    if (row >= N_DST) return;
    float acc[8] = {0, 0, 0, 0, 0, 0, 0, 0};
    const float* fr = feat_dst + (size_t)row * 256;
    for (int k = lane; k < 256; k += 32) {
        float f = fr[k];
#pragma unroll
        for (int h = 0; h < 8; h++) acc[h] += f * sw[h * 256 + k];
    }
#pragma unroll
    for (int h = 0; h < 8; h++)
#pragma unroll
        for (int o = 16; o; o >>= 1) acc[h] += __shfl_xor_sync(~0u, acc[h], o);
    if (lane == 0) {
#pragma unroll
        for (int h = 0; h < 8; h++) g_edst[row * 8 + h] = acc[h];
    }
}

// ---------------- 3. fs = feat_src @ src_w  (single-plane fp16 A x fp16 B) -----
__device__ __forceinline__ void mma16816h(float* c, unsigned a0, unsigned a1,
                                          unsigned a2, unsigned a3,
                                          unsigned b0, unsigned b1) {
    asm("mma.sync.aligned.m16n8k16.row.col.f32.f16.f16.f32 "
        "{%0,%1,%2,%3},{%4,%5,%6,%7},{%8,%9},{%0,%1,%2,%3};"
        : "+f"(c[0]), "+f"(c[1]), "+f"(c[2]), "+f"(c[3])
        : "r"(a0), "r"(a1), "r"(a2), "r"(a3), "r"(b0), "r"(b1));
}
__device__ __forceinline__ void ldsm4(unsigned& r0, unsigned& r1, unsigned& r2,
                                      unsigned& r3, unsigned addr) {
    asm volatile("ldmatrix.sync.aligned.m8n8.x4.shared.b16 {%0,%1,%2,%3}, [%4];"
                 : "=r"(r0), "=r"(r1), "=r"(r2), "=r"(r3) : "r"(addr));
}

__global__ __launch_bounds__(256, 2) void gemm_fp16(const float* __restrict__ A) {
    __shared__ __align__(16) __half sA[128][40];   // [m][k]
    __shared__ __align__(16) __half sB[64][40];    // [n][k]

    const int tid = threadIdx.x;
    const int bm = blockIdx.y * 128;
    const int bn = blockIdx.x * 64;
    const int wid = tid >> 5, lane = tid & 31;
    const int wm = wid & 3, wn = wid >> 2;   // 4x2 warp grid, warp tile 32x32

    float c[2][4][4];
#pragma unroll
    for (int i = 0; i < 2; i++)
#pragma unroll
        for (int j = 0; j < 4; j++)
#pragma unroll
            for (int k = 0; k < 4; k++) c[i][j][k] = 0.f;

    float4 pa[4];
    uint4 pb;
#pragma unroll
    for (int i = 0; i < 4; i++) {
        int q = tid + 256 * i;
        int r = q >> 3, c4 = (q & 7) * 4;
        int row = bm + r;
        pa[i] = (row < N_SRC) ? *(const float4*)(A + (size_t)row * 256 + c4)
                              : make_float4(0.f, 0.f, 0.f, 0.f);
    }
    {
        int n = tid >> 2, kc = (tid & 3) * 8;
        pb = *(const uint4*)(g_Bt + (size_t)(bn + n) * 256 + kc);
    }

    const unsigned sA_b = (unsigned)__cvta_generic_to_shared(&sA[0][0]);
    const unsigned sB_b = (unsigned)__cvta_generic_to_shared(&sB[0][0]);
    const int l = lane;
    const unsigned aoff =
        (((wm * 32 + (l & 7) + ((l >> 3) & 1) * 8) * 40) + ((l >> 4) & 1) * 8) * 2;
    const unsigned boff =
        (((wn * 32 + (l & 7) + ((l >> 4) & 1) * 8) * 40) + ((l >> 3) & 1) * 8) * 2;

    for (int kt = 0; kt < 8; kt++) {
#pragma unroll
        for (int i = 0; i < 4; i++) {
            int q = tid + 256 * i;
            int r = q >> 3, c4 = (q & 7) * 4;
            float4 v = pa[i];
            *(__half2*)&sA[r][c4] = __floats2half2_rn(v.x, v.y);
            *(__half2*)&sA[r][c4 + 2] = __floats2half2_rn(v.z, v.w);
        }
        {
            int n = tid >> 2, kc = (tid & 3) * 8;
            *(uint4*)&sB[n][kc] = pb;
        }
        __syncthreads();

        if (kt < 7) {
#pragma unroll
            for (int i = 0; i < 4; i++) {
                int q = tid + 256 * i;
                int r = q >> 3, c4 = (q & 7) * 4;
                int row = bm + r;
                pa[i] = (row < N_SRC)
                            ? *(const float4*)(A + (size_t)row * 256 + (kt + 1) * 32 + c4)
                            : make_float4(0.f, 0.f, 0.f, 0.f);
            }
            int n = tid >> 2, kc = (tid & 3) * 8;
            pb = *(const uint4*)(g_Bt + (size_t)(bn + n) * 256 + (kt + 1) * 32 + kc);
        }

#pragma unroll
        for (int s = 0; s < 2; s++) {
            unsigned ah[2][4], bb[4][2];
#pragma unroll
            for (int ia = 0; ia < 2; ia++) {
                unsigned off = aoff + (ia * 640 + s * 16) * 2;
                ldsm4(ah[ia][0], ah[ia][1], ah[ia][2], ah[ia][3], sA_b + off);
            }
#pragma unroll
            for (int p = 0; p < 2; p++) {
                unsigned off = boff + (p * 640 + s * 16) * 2;
                ldsm4(bb[2 * p][0], bb[2 * p][1], bb[2 * p + 1][0], bb[2 * p + 1][1],
                      sB_b + off);
            }
#pragma unroll
            for (int ia = 0; ia < 2; ia++)
#pragma unroll
                for (int ja = 0; ja < 4; ja++)
                    mma16816h(c[ia][ja], ah[ia][0], ah[ia][1], ah[ia][2], ah[ia][3],
                              bb[ja][0], bb[ja][1]);
        }
        if (kt < 7) __syncthreads();
    }

    // epilogue 1: fp32 accumulators -> fp16 fs
    const int tq = lane >> 2, tr = lane & 3;
#pragma unroll
    for (int ia = 0; ia < 2; ia++) {
        int row0 = bm + wm * 32 + ia * 16 + tq;
#pragma unroll
        for (int ja = 0; ja < 4; ja++) {
            int col = bn + wn * 32 + ja * 8 + 2 * tr;
            if (row0 < N_SRC)
                *(__half2*)&g_fs[(size_t)row0 * 256 + col] =
                    __floats2half2_rn(c[ia][ja][0], c[ia][ja][1]);
            if (row0 + 8 < N_SRC)
                *(__half2*)&g_fs[(size_t)(row0 + 8) * 256 + col] =
                    __floats2half2_rn(c[ia][ja][2], c[ia][ja][3]);
        }
    }

    // epilogue 2: fused e_src — this warp's 32 cols = exactly one head
    {
        const int hd = (bn + wn * 32) >> 5;
        float rE[8];
#pragma unroll
        for (int ja = 0; ja < 4; ja++) {
            int col = bn + wn * 32 + ja * 8 + 2 * tr;
            rE[ja * 2]     = g_relE[col];
            rE[ja * 2 + 1] = g_relE[col + 1];
        }
#pragma unroll
        for (int ia = 0; ia < 2; ia++) {
            float p0 = 0.f, p8 = 0.f;
#pragma unroll
            for (int ja = 0; ja < 4; ja++) {
                p0 += c[ia][ja][0] * rE[ja * 2] + c[ia][ja][1] * rE[ja * 2 + 1];
                p8 += c[ia][ja][2] * rE[ja * 2] + c[ia][ja][3] * rE[ja * 2 + 1];
            }
            p0 += __shfl_xor_sync(~0u, p0, 1);
            p0 += __shfl_xor_sync(~0u, p0, 2);
            p8 += __shfl_xor_sync(~0u, p8, 1);
            p8 += __shfl_xor_sync(~0u, p8, 2);
            int row0 = bm + wm * 32 + ia * 16 + tq;
            if (tr == 0) {
                if (row0 < N_SRC) g_esrc[row0 * 8 + hd] = p0;
                if (row0 + 8 < N_SRC) g_esrc[(row0 + 8) * 8 + hd] = p8;
            }
        }
    }
}

// ---------------- 4. three-phase exclusive scan ---------------------------------
__global__ __launch_bounds__(256) void scanA_kernel() {
    __shared__ int sh[256];
    int t = threadIdx.x;
    int i = blockIdx.x * 256 + t;
    sh[t] = (i < N_DST) ? g_count[i] : 0;
    __syncthreads();
#pragma unroll
    for (int off = 128; off; off >>= 1) {
        if (t < off) sh[t] += sh[t + off];
        __syncthreads();
    }
    if (t == 0) g_part[blockIdx.x] = sh[0];
}

__global__ __launch_bounds__(256) void scanB_kernel() {
    __shared__ int sh[256];
    int t = threadIdx.x;
    int v = (t < NCHUNK) ? g_part[t] : 0;
    sh[t] = v;
    __syncthreads();
#pragma unroll
    for (int off = 1; off < 256; off <<= 1) {
        int x = (t >= off) ? sh[t - off] : 0;
        __syncthreads();
        sh[t] += x;
        __syncthreads();
    }
    if (t < NCHUNK) g_part[t] = sh[t] - v;
    if (t == 255) g_off[N_DST] = sh[255];
}

// scanC also re-zeroes g_count so the fused prep-histogram of the NEXT pass
// starts from zeros (keeps every pipeline pass state-neutral for graph replay).
__global__ __launch_bounds__(256) void scanC_kernel() {
    __shared__ int sh[256];
    int t = threadIdx.x;
    int i = blockIdx.x * 256 + t;
    int v = (i < N_DST) ? g_count[i] : 0;
    sh[t] = v;
    __syncthreads();
#pragma unroll
    for (int off = 1; off < 256; off <<= 1) {
        int x = (t >= off) ? sh[t - off] : 0;
        __syncthreads();
        sh[t] += x;
        __syncthreads();
    }
    if (i < N_DST) {
        int excl = sh[t] - v + g_part[blockIdx.x];
        g_off[i] = excl;
        g_cursor[i] = excl;
        g_count[i] = 0;
    }
}

// ---------------- 5. scatter src ids into CSR slots ----------------------------
__global__ __launch_bounds__(256) void scatter_kernel(const int* __restrict__ src_idx,
                                                      const int* __restrict__ dst_idx) {
    int e = blockIdx.x * 256 + threadIdx.x;
    if (e >= NEDGE) return;
    int t = dst_idx[e];
    int p = atomicAdd(&g_cursor[t], 1);
    g_srcs[p] = src_idx[e];
}

// ---------------- 6. fused softmax + aggregation (R10 structure, fp16 fs) ------
__global__ __launch_bounds__(256) void edge_agg(float* __restrict__ out) {
    int warp = threadIdx.x >> 5, lane = threadIdx.x & 31;
    int dst = blockIdx.x * 8 + warp;
    if (dst >= N_DST) return;
    const int beg = g_off[dst], end = g_off[dst + 1];
    const int h = lane >> 2;
    const float ed = g_edst[dst * 8 + h];
    const int col = lane * 8;

    float dsum = 0.f;
    float acc0 = 0, acc1 = 0, acc2 = 0, acc3 = 0, acc4 = 0, acc5 = 0, acc6 = 0, acc7 = 0;

    int i = beg;
    for (; i + 4 <= end; i += 4) {
        int s0 = __ldg(&g_srcs[i]);
        int s1 = __ldg(&g_srcs[i + 1]);
        int s2 = __ldg(&g_srcs[i + 2]);
        int s3 = __ldg(&g_srcs[i + 3]);
        float e0 = __ldg(&g_esrc[s0 * 8 + h]);
        float e1 = __ldg(&g_esrc[s1 * 8 + h]);
        float e2 = __ldg(&g_esrc[s2 * 8 + h]);
        float e3 = __ldg(&g_esrc[s3 * 8 + h]);
        uint4 u0 = *(const uint4*)(g_fs + (size_t)s0 * 256 + col);
        uint4 u1 = *(const uint4*)(g_fs + (size_t)s1 * 256 + col);
        uint4 u2 = *(const uint4*)(g_fs + (size_t)s2 * 256 + col);
        uint4 u3 = *(const uint4*)(g_fs + (size_t)s3 * 256 + col);
        float v0 = e0 + ed; v0 = v0 > 0.f ? v0 : NEG * v0;
        float v1 = e1 + ed; v1 = v1 > 0.f ? v1 : NEG * v1;
        float v2 = e2 + ed; v2 = v2 > 0.f ? v2 : NEG * v2;
        float v3 = e3 + ed; v3 = v3 > 0.f ? v3 : NEG * v3;
        float a0 = __expf(v0), a1 = __expf(v1), a2 = __expf(v2), a3 = __expf(v3);
        dsum += (a0 + a1) + (a2 + a3);
#define ACC_EDGE(u, a)                                                        \
        {                                                                     \
            float2 p0 = __half22float2(*(const __half2*)&(u).x);              \
            float2 p1 = __half22float2(*(const __half2*)&(u).y);              \
            float2 p2 = __half22float2(*(const __half2*)&(u).z);              \
            float2 p3 = __half22float2(*(const __half2*)&(u).w);              \
            acc0 += (a) * p0.x; acc1 += (a) * p0.y;                           \
            acc2 += (a) * p1.x; acc3 += (a) * p1.y;                           \
            acc4 += (a) * p2.x; acc5 += (a) * p2.y;                           \
            acc6 += (a) * p3.x; acc7 += (a) * p3.y;                           \
        }
        ACC_EDGE(u0, a0)
        ACC_EDGE(u1, a1)
        ACC_EDGE(u2, a2)
        ACC_EDGE(u3, a3)
    }
    for (; i < end; i++) {
        int s = __ldg(&g_srcs[i]);
        float es = __ldg(&g_esrc[s * 8 + h]);
        float v = es + ed;
        v = v > 0.f ? v : NEG * v;
        float a = __expf(v);
        dsum += a;
        uint4 u = *(const uint4*)(g_fs + (size_t)s * 256 + col);
        ACC_EDGE(u, a)
    }
#undef ACC_EDGE
    const float dinv = 1.0f / dsum;
    float4* o = (float4*)(out + (size_t)dst * 256 + col);
    // fmaxf(NaN, 0) == 0 handles the empty-segment (0 * inf) case
    o[0] = make_float4(fmaxf(acc0 * dinv, 0.f), fmaxf(acc1 * dinv, 0.f),
                       fmaxf(acc2 * dinv, 0.f), fmaxf(acc3 * dinv, 0.f));
    o[1] = make_float4(fmaxf(acc4 * dinv, 0.f), fmaxf(acc5 * dinv, 0.f),
                       fmaxf(acc6 * dinv, 0.f), fmaxf(acc7 * dinv, 0.f));
}

// ---------------- launch: 3-way fork ---------------------------------------------
// s0: prep+hist -> gemm ; s1: scans -> scatter ; s2: gemv ; join -> edge_agg
extern "C" void kernel_launch(void* const* d_in, const int* in_sizes, int n_in,
                              void* d_out, int out_size) {
    const float* feat_src = (const float*)d_in[0];
    const float* feat_dst = (const float*)d_in[1];
    const float* src_w    = (const float*)d_in[2];
    const float* dst_w    = (const float*)d_in[3];
    const float* rel_emb  = (const float*)d_in[4];
    const float* rel_w    = (const float*)d_in[5];
    const int*   src_idx  = (const int*)d_in[6];
    const int*   dst_idx  = (const int*)d_in[7];
    float* out = (float*)d_out;

    static cudaStream_t s1 = nullptr, s2 = nullptr;
    static cudaEvent_t e_prep = nullptr, e_csr = nullptr, e_gemv = nullptr;
    if (!s1) {
        cudaStreamCreateWithFlags(&s1, cudaStreamNonBlocking);
        cudaStreamCreateWithFlags(&s2, cudaStreamNonBlocking);
        cudaEventCreateWithFlags(&e_prep, cudaEventDisableTiming);
        cudaEventCreateWithFlags(&e_csr, cudaEventDisableTiming);
        cudaEventCreateWithFlags(&e_gemv, cudaEventDisableTiming);
    }

    prep_kernel<<<256, 256>>>(rel_emb, rel_w, src_w, dst_w, dst_idx);
    cudaEventRecord(e_prep, 0);

    // CSR branch (scan + scatter) on s1
    cudaStreamWaitEvent(s1, e_prep, 0);
    scanA_kernel<<<NCHUNK, 256, 0, s1>>>();
    scanB_kernel<<<1, 256, 0, s1>>>();
    scanC_kernel<<<NCHUNK, 256, 0, s1>>>();
    scatter_kernel<<<(NEDGE + 255) / 256, 256, 0, s1>>>(src_idx, dst_idx);
    cudaEventRecord(e_csr, s1);

    // e_dst GEMV on s2 (feeds only edge_agg)
    cudaStreamWaitEvent(s2, e_prep, 0);
    gemv_dst<<<(N_DST + 7) / 8, 256, 0, s2>>>(feat_dst);
    cudaEventRecord(e_gemv, s2);

    // GEMM branch on the default stream — runs concurrently with s1/s2
    gemm_fp16<<<dim3(4, (N_SRC + 127) / 128), 256>>>(feat_src);

    // join all, then aggregate
    cudaStreamWaitEvent(0, e_csr, 0);
    cudaStreamWaitEvent(0, e_gemv, 0);
    edge_agg<<<(N_DST + 7) / 8, 256>>>(out);
}